// round 11
// baseline (speedup 1.0000x reference)
#include <cuda_runtime.h>
#include <cstdint>

// ---------------------------------------------------------------------------
// Problem constants
// ---------------------------------------------------------------------------
#define B_   32
#define C_   256
#define NX   961
#define NZ   49
#define XT_LD  256
#define ZZ_LD  64
#define CT_LD  768      // CATT row stride
#define CT_ROWS 992     // CATT rows padded (zero rows 961..991)
#define PS_LD  992
#define PZ_LD  64

#define BM 128
#define BK 32
#define AW 4096                 // A tile words (128*32)
#define STW 8192                // words per stage (A+B)
#define SMEMB (3 * STW * 4)     // 96 KB, 3-stage

// ---------------------------------------------------------------------------
// Scratch (device globals; zero-initialized, never freed)
// ---------------------------------------------------------------------------
__device__ float g_ZFT[(size_t)B_ * NZ * 256];        // zf^T   [B][Nz][C] (tf32)
__device__ float g_XT [(size_t)B_ * NX * XT_LD];      // xf_trans^T (tf32)
__device__ float g_ZZ [(size_t)B_ * 512 * ZZ_LD];     // [zf_g; zf_trans]
__device__ float g_CT [(size_t)B_ * CT_ROWS * CT_LD]; // [emb|self|xg] n-major
__device__ float g_PS [(size_t)B_ * NX * PS_LD];      // self probs (tf32)
__device__ float g_PZ [(size_t)B_ * NX * PZ_LD];      // cross probs (tf32)
__device__ float g_WR [393216];                       // rounded [Wq|Wg|Ws|Wfi]

// ---------------------------------------------------------------------------
__device__ __forceinline__ uint32_t cvt_tf32(float f) {
    uint32_t r;
    asm("cvt.rna.tf32.f32 %0, %1;" : "=r"(r) : "f"(f));
    return r;
}
__device__ __forceinline__ float round_tf32f(float f) {
    return __uint_as_float(cvt_tf32(f));
}
__device__ __forceinline__ uint32_t smem_u32(const void* p) {
    uint32_t a;
    asm("{ .reg .u64 t; cvta.to.shared.u64 t, %1; cvt.u32.u64 %0, t; }" : "=r"(a) : "l"(p));
    return a;
}
__device__ __forceinline__ void cp16(uint32_t dst, const float* src, int ss) {
    asm volatile("cp.async.cg.shared.global [%0], [%1], 16, %2;"
                 :: "r"(dst), "l"(src), "r"(ss));
}
#define CP_COMMIT() asm volatile("cp.async.commit_group;" ::: "memory")
#define CP_WAIT0()  asm volatile("cp.async.wait_group 0;" ::: "memory")
#define CP_WAIT1()  asm volatile("cp.async.wait_group 1;" ::: "memory")

__device__ __forceinline__ void mma_tf32(float* d, const uint32_t* a, const uint32_t* b) {
    asm volatile(
        "mma.sync.aligned.m16n8k8.row.col.f32.tf32.tf32.f32 "
        "{%0,%1,%2,%3}, {%4,%5,%6,%7}, {%8,%9}, {%0,%1,%2,%3};"
        : "+f"(d[0]), "+f"(d[1]), "+f"(d[2]), "+f"(d[3])
        : "r"(a[0]), "r"(a[1]), "r"(a[2]), "r"(a[3]), "r"(b[0]), "r"(b[1]));
}
__device__ __forceinline__ void ldsm4(uint32_t& r0, uint32_t& r1, uint32_t& r2, uint32_t& r3,
                                      uint32_t addr) {
    asm volatile("ldmatrix.sync.aligned.m8n8.x4.shared.b16 {%0,%1,%2,%3}, [%4];"
                 : "=r"(r0), "=r"(r1), "=r"(r2), "=r"(r3) : "r"(addr));
}

// ---------------------------------------------------------------------------
// Stagers: per-thread state hoisted out of the mainloop.
// Cp: cp.async, src row-major-k (tf32, ld mult of 4, k-tile within row)
// Tr<CVT>: transpose, src[k][n]: 4 strided (n-coalesced) loads + STS.128,
//          conflict-free; CVT applies tf32 rounding (for raw fp32 sources).
// ---------------------------------------------------------------------------
struct StagerCp {
    const float* p[4];
    uint32_t dst[4];
    int sz[4];
    __device__ __forceinline__ void init(const float* src, int ld, int r0, int rmax, int t) {
#pragma unroll
        for (int i = 0; i < 4; i++) {
            int q = i * 256 + t;
            int row = q >> 3, u = q & 7;
            bool ok = (r0 + row < rmax);
            p[i] = ok ? (src + (size_t)(r0 + row) * ld + u * 4) : src;
            sz[i] = ok ? 16 : 0;
            dst[i] = (uint32_t)(((row << 5) + ((u ^ (row & 7)) << 2)) * 4);
        }
    }
    __device__ __forceinline__ void issue(uint32_t sb) {
#pragma unroll
        for (int i = 0; i < 4; i++) {
            cp16(sb + dst[i], p[i], sz[i]);
            p[i] += BK;
        }
    }
};
template<bool CVT>
struct StagerTr {
    const float* p[4];
    uint32_t dst[4];
    bool ok[4];
    int ld;
    __device__ __forceinline__ void init(const float* src, int ld_, int r0, int rmax, int t) {
        ld = ld_;
#pragma unroll
        for (int i = 0; i < 4; i++) {
            int q = i * 256 + t;
            int lr = q & 127, g = q >> 7;
            int n = r0 + lr;
            ok[i] = (n < rmax);
            p[i] = ok[i] ? (src + (size_t)(g * 4) * ld_ + n) : src;
            dst[i] = (uint32_t)((lr << 5) + ((g ^ (lr & 7)) << 2));
        }
    }
    __device__ __forceinline__ void issue(uint32_t* sw) {
#pragma unroll
        for (int i = 0; i < 4; i++) {
            uint4 w = make_uint4(0u, 0u, 0u, 0u);
            if (ok[i]) {
                const float* s = p[i];
                if (CVT) {
                    w.x = cvt_tf32(s[0]);
                    w.y = cvt_tf32(s[(size_t)ld]);
                    w.z = cvt_tf32(s[(size_t)2 * ld]);
                    w.w = cvt_tf32(s[(size_t)3 * ld]);
                } else {
                    w.x = __float_as_uint(s[0]);
                    w.y = __float_as_uint(s[(size_t)ld]);
                    w.z = __float_as_uint(s[(size_t)2 * ld]);
                    w.w = __float_as_uint(s[(size_t)3 * ld]);
                }
            }
            *reinterpret_cast<uint4*>(sw + dst[i]) = w;
            p[i] += (size_t)BK * ld;
        }
    }
};

// ---------------------------------------------------------------------------
// tf32 GEMM: D[m][n] = epi( sum_k A[m][k] * B[n][k] ), tile 128x128x32,
// 256 threads, 3-stage cp.async pipeline (prefetch-first), LDSM fragments.
// K (=KK) is compile-time; T = KK/BK.
// LA/LB: 0=Cp, 1=Tr, 2=TrCvt
// EPI 1: relu(bn per row m)
// EPI 2: plain
// EPI 4: Z-stack rows: r<256 relu(bn[r], bias) ; r>=256 +bias2[r-256]
// EPI 5: col split: c<256 +bias[c] -> D ; c>=256 relu(bn[c-256], bias2) -> D2
// ---------------------------------------------------------------------------
template<int LA, int LB, int EPI, bool ROUND, int KK>
__global__ void __launch_bounds__(256, 2) mm(
    const float* __restrict__ A, const float* __restrict__ Bm,
    float* __restrict__ D, float* __restrict__ D2,
    const float* __restrict__ bias, const float* __restrict__ bias2,
    const float* __restrict__ gamma, const float* __restrict__ beta,
    const float* __restrict__ mean, const float* __restrict__ var,
    int M, int N, int lda, int ldb, int ldd,
    long abs_, long bbs_, long dbs_, long d2bs_)
{
    constexpr int T = KK / BK;

    extern __shared__ uint32_t smem[];
    const uint32_t sbyte = smem_u32(smem);

    const int t = threadIdx.x;
    const int wid = t >> 5, lane = t & 31;
    const int warp_m = wid & 3, warp_n = wid >> 2;
    const int qid = lane >> 2, qtid = lane & 3;
    const int b = blockIdx.z;
    const int n0 = blockIdx.x * 128;
    const int m0 = blockIdx.y * BM;

    const float* Ab = A + (long)b * abs_;
    const float* Bb = Bm + (long)b * bbs_;
    float* Db = D + (long)b * dbs_;

    float acc[2][8][4];
#pragma unroll
    for (int i = 0; i < 2; i++)
#pragma unroll
        for (int j = 0; j < 8; j++)
#pragma unroll
            for (int k = 0; k < 4; k++) acc[i][j][k] = 0.f;

    // LDSM per-thread address bases (byte offsets inside a stage's A/B tile).
    const int jm = lane >> 3, r7 = lane & 7;
    const uint32_t aoffb = ((uint32_t)(warp_m * 32 + (jm & 1) * 8 + r7) << 7)
                         + ((uint32_t)(((jm >> 1) ^ (lane & 1))) << 4);
    const uint32_t boffb = ((uint32_t)(warp_n * 64 + (jm >> 1) * 8 + r7) << 7)
                         + ((uint32_t)(((jm & 1) ^ (lane & 1))) << 4);
    const uint32_t rq64 = (uint32_t)(lane & 6) << 4;

    StagerCp saC, sbC;
    StagerTr<(LA == 2)> saT;
    StagerTr<(LB == 2)> sbT;
    if (LA == 0) saC.init(Ab, lda, m0, M, t);
    else         saT.init(Ab, lda, m0, M, t);
    if (LB == 0) sbC.init(Bb, ldb, n0, N, t);
    else         sbT.init(Bb, ldb, n0, N, t);

    auto issueA = [&](int s) {
        if (LA == 0) saC.issue(sbyte + s * (STW * 4));
        else         saT.issue(smem + s * STW);
    };
    auto issueB = [&](int s) {
        if (LB == 0) sbC.issue(sbyte + s * (STW * 4) + AW * 4);
        else         sbT.issue(smem + s * STW + AW);
    };

    // prologue: stages 0 and 1
    issueA(0); issueB(0);
    CP_COMMIT();
    if (T > 1) {
        issueA(1); issueB(1);
        CP_COMMIT();
    }

    int stg = 0;
#pragma unroll 3
    for (int tt = 0; tt < T; tt++) {
        if (tt + 1 < T) CP_WAIT1(); else CP_WAIT0();
        __syncthreads();

        // prefetch-first: issue tile tt+2 before the compute burst
        if (tt + 2 < T) {
            int s2 = stg + 2; if (s2 >= 3) s2 -= 3;
            issueA(s2); issueB(s2);
            CP_COMMIT();
        }

        const uint32_t sAb = sbyte + (uint32_t)stg * (STW * 4) + aoffb;
        const uint32_t sBb = sbyte + (uint32_t)stg * (STW * 4) + (AW * 4) + boffb;
#pragma unroll
        for (int ks = 0; ks < 4; ks++) {
            const uint32_t tk = ((uint32_t)(32 * ks)) ^ rq64;
            uint32_t afr[2][4];
            ldsm4(afr[0][0], afr[0][1], afr[0][2], afr[0][3], sAb + tk);
            ldsm4(afr[1][0], afr[1][1], afr[1][2], afr[1][3], sAb + tk + 2048);
            uint32_t bfr[8][2];
            ldsm4(bfr[0][0], bfr[0][1], bfr[1][0], bfr[1][1], sBb + tk);
            ldsm4(bfr[2][0], bfr[2][1], bfr[3][0], bfr[3][1], sBb + tk + 2048);
            ldsm4(bfr[4][0], bfr[4][1], bfr[5][0], bfr[5][1], sBb + tk + 4096);
            ldsm4(bfr[6][0], bfr[6][1], bfr[7][0], bfr[7][1], sBb + tk + 6144);
#pragma unroll
            for (int im = 0; im < 2; im++)
#pragma unroll
                for (int jn = 0; jn < 8; jn++)
                    mma_tf32(acc[im][jn], afr[im], bfr[jn]);
        }
        stg++; if (stg == 3) stg = 0;
    }

    // ---- epilogue ----
    const int mb = m0 + warp_m * 32;
    const int nb = n0 + warp_n * 64;

    float scl[2][2], sft[2][2];
    if (EPI == 1 || EPI == 4) {
#pragma unroll
        for (int im = 0; im < 2; im++)
#pragma unroll
            for (int h = 0; h < 2; h++) {
                int r = mb + im * 16 + qid + h * 8;
                if (EPI == 1) {
                    int ri = (r < M) ? r : 0;
                    float inv = rsqrtf(var[ri] + 1e-5f);
                    float s = gamma[ri] * inv;
                    scl[im][h] = s;
                    sft[im][h] = (bias[ri] - mean[ri]) * s + beta[ri];
                } else {
                    if (r < 256) {
                        float inv = rsqrtf(var[r] + 1e-5f);
                        float s = gamma[r] * inv;
                        scl[im][h] = s;
                        sft[im][h] = (bias[r] - mean[r]) * s + beta[r];
                    } else {
                        scl[im][h] = 1.f;
                        sft[im][h] = bias2[(r < M) ? (r - 256) : 0];
                    }
                }
            }
    }

    // EPI5: precompute per-column params once (16 columns per thread)
    float cscl[16], csft[16];
    if (EPI == 5) {
#pragma unroll
        for (int jn = 0; jn < 8; jn++)
#pragma unroll
            for (int e = 0; e < 2; e++) {
                int c = nb + jn * 8 + 2 * qtid + e;
                int idx = jn * 2 + e;
                if (c < 256) {
                    cscl[idx] = 1.f;
                    csft[idx] = bias[c];
                } else {
                    int ci = c - 256;
                    float inv = rsqrtf(var[ci] + 1e-5f);
                    float s = gamma[ci] * inv;
                    cscl[idx] = s;
                    csft[idx] = (bias2[ci] - mean[ci]) * s + beta[ci];
                }
            }
    }

    float* D2b = (EPI == 5) ? (D2 + (long)b * d2bs_) : nullptr;

#pragma unroll
    for (int im = 0; im < 2; im++) {
#pragma unroll
        for (int jn = 0; jn < 8; jn++) {
            int c0 = nb + jn * 8 + 2 * qtid;
#pragma unroll
            for (int h = 0; h < 2; h++) {
                int r = mb + im * 16 + qid + h * 8;
                if (r >= M) continue;
                float v0 = acc[im][jn][h * 2 + 0];
                float v1 = acc[im][jn][h * 2 + 1];
                if (EPI == 1) {
                    v0 = fmaxf(v0 * scl[im][h] + sft[im][h], 0.f);
                    v1 = fmaxf(v1 * scl[im][h] + sft[im][h], 0.f);
                }
                if (EPI == 4) {
                    v0 = v0 * scl[im][h] + sft[im][h];
                    v1 = v1 * scl[im][h] + sft[im][h];
                    if (r < 256) { v0 = fmaxf(v0, 0.f); v1 = fmaxf(v1, 0.f); }
                }
                if (EPI == 5) {
#pragma unroll
                    for (int e = 0; e < 2; e++) {
                        int c = c0 + e;
                        int idx = jn * 2 + e;
                        float v = e ? v1 : v0;
                        v = v * cscl[idx] + csft[idx];
                        if (c >= 256) v = fmaxf(v, 0.f);
                        if (ROUND) v = round_tf32f(v);
                        if (c < 256) Db[(long)r * ldd + c] = v;
                        else         D2b[(long)r * CT_LD + (c - 256)] = v;
                    }
                    continue;
                }
                if (ROUND) { v0 = round_tf32f(v0); v1 = round_tf32f(v1); }
                if (c0 < N)     Db[(long)r * ldd + c0]     = v0;
                if (c0 + 1 < N) Db[(long)r * ldd + c0 + 1] = v1;
            }
        }
    }
}

// ---------------------------------------------------------------------------
// Row softmax (row length M <= 1024, padded stride ld); stores tf32-rounded.
// ---------------------------------------------------------------------------
__global__ void softmax_rows(float* __restrict__ L, int M, int ld)
{
    float* p = L + (size_t)blockIdx.x * ld;
    const int t = threadIdx.x;

    float r[4];
    float mx = -1e30f;
#pragma unroll
    for (int i = 0; i < 4; i++) {
        int idx = t + i * 256;
        r[i] = (idx < M) ? p[idx] : -1e30f;
        mx = fmaxf(mx, r[i]);
    }
#pragma unroll
    for (int off = 16; off; off >>= 1)
        mx = fmaxf(mx, __shfl_xor_sync(0xffffffffu, mx, off));

    __shared__ float redmax[8];
    __shared__ float redsum[8];
    if ((t & 31) == 0) redmax[t >> 5] = mx;
    __syncthreads();
    mx = redmax[0];
#pragma unroll
    for (int w = 1; w < 8; w++) mx = fmaxf(mx, redmax[w]);

    float s = 0.f;
#pragma unroll
    for (int i = 0; i < 4; i++) {
        int idx = t + i * 256;
        r[i] = (idx < M) ? __expf(r[i] - mx) : 0.f;
        s += r[i];
    }
#pragma unroll
    for (int off = 16; off; off >>= 1)
        s += __shfl_xor_sync(0xffffffffu, s, off);
    if ((t & 31) == 0) redsum[t >> 5] = s;
    __syncthreads();
    s = 0.f;
#pragma unroll
    for (int w = 0; w < 8; w++) s += redsum[w];

    float inv = 1.f / s;
#pragma unroll
    for (int i = 0; i < 4; i++) {
        int idx = t + i * 256;
        if (idx < M) p[idx] = round_tf32f(r[i] * inv);
    }
}

// ---------------------------------------------------------------------------
// src [B][256][Ns] -> dst [B][Ns][256], tf32-rounded. Dense batch stride.
// ---------------------------------------------------------------------------
__global__ void transpose_round(const float* __restrict__ src, float* __restrict__ dst, int Ns)
{
    __shared__ float tl[32][33];
    const int b = blockIdx.z;
    const int n0 = blockIdx.x * 32, c0 = blockIdx.y * 32;
    const int tx = threadIdx.x & 31, ty = threadIdx.x >> 5;
    const float* s = src + (size_t)b * 256 * Ns;
    float* d = dst + (size_t)b * Ns * 256;
#pragma unroll
    for (int i = 0; i < 4; i++) {
        int c = c0 + ty + i * 8, n = n0 + tx;
        tl[ty + i * 8][tx] = (n < Ns) ? s[(size_t)c * Ns + n] : 0.f;
    }
    __syncthreads();
#pragma unroll
    for (int i = 0; i < 4; i++) {
        int n = n0 + ty + i * 8, c = c0 + tx;
        if (n < Ns) d[(size_t)n * 256 + c] = round_tf32f(tl[tx][ty + i * 8]);
    }
}

// ---------------------------------------------------------------------------
// Pre-round weights into g_WR: [Wq | Wg | Ws | Wfi]
// ---------------------------------------------------------------------------
__global__ void round_weights(const float* __restrict__ wq, const float* __restrict__ ws,
                              const float* __restrict__ wg, const float* __restrict__ wfi,
                              float* __restrict__ o)
{
    for (int i = blockIdx.x * 256 + threadIdx.x; i < 393216; i += gridDim.x * 256) {
        float v;
        if      (i < 65536)  v = wq [i];
        else if (i < 131072) v = wg [i - 65536];
        else if (i < 196608) v = ws [i - 131072];
        else                 v = wfi[i - 196608];
        o[i] = round_tf32f(v);
    }
}

// ---------------------------------------------------------------------------
extern "C" void kernel_launch(void* const* d_in, const int* in_sizes, int n_in,
                              void* d_out, int out_size)
{
    const float* zf  = (const float*)d_in[0];
    const float* xf  = (const float*)d_in[1];
    const float* Wq  = (const float*)d_in[2];
    const float* bq  = (const float*)d_in[3];
    const float* Ws_ = (const float*)d_in[4];
    const float* bs  = (const float*)d_in[5];
    const float* Wg  = (const float*)d_in[6];
    const float* bg  = (const float*)d_in[7];
    const float* g_gamma = (const float*)d_in[8];
    const float* g_beta  = (const float*)d_in[9];
    const float* g_mean  = (const float*)d_in[10];
    const float* g_var   = (const float*)d_in[11];
    const float* Wfi = (const float*)d_in[12];
    const float* bfi = (const float*)d_in[13];
    const float* fi_gamma = (const float*)d_in[14];
    const float* fi_beta  = (const float*)d_in[15];
    const float* fi_mean  = (const float*)d_in[16];
    const float* fi_var   = (const float*)d_in[17];
    float* out = (float*)d_out;

    float *ZFT, *XT, *ZZ, *CT, *PS, *PZ, *WR;
    cudaGetSymbolAddress((void**)&ZFT, g_ZFT);
    cudaGetSymbolAddress((void**)&XT,  g_XT);
    cudaGetSymbolAddress((void**)&ZZ,  g_ZZ);
    cudaGetSymbolAddress((void**)&CT,  g_CT);
    cudaGetSymbolAddress((void**)&PS,  g_PS);
    cudaGetSymbolAddress((void**)&PZ,  g_PZ);
    cudaGetSymbolAddress((void**)&WR,  g_WR);

#define SETUP(KER) do { \
    cudaFuncSetAttribute(KER, cudaFuncAttributeMaxDynamicSharedMemorySize, SMEMB); \
    cudaFuncSetAttribute(KER, cudaFuncAttributePreferredSharedMemoryCarveout, 100); \
} while (0)
    SETUP((mm<2,0,5,true ,256>));
    SETUP((mm<0,0,4,true ,256>));
    SETUP((mm<0,0,2,false,256>));
    SETUP((mm<0,1,2,false,256>));
    SETUP((mm<0,1,2,true ,992>));
    SETUP((mm<0,0,2,true ,64 >));
    SETUP((mm<0,0,1,false,768>));
#undef SETUP

    const long CNX    = (long)C_ * NX;
    const long ZFT_BS = (long)NZ * 256;
    const long XT_BS  = (long)NX * XT_LD;
    const long ZZ_BS  = (long)512 * ZZ_LD;
    const long CT_BS  = (long)CT_ROWS * CT_LD;
    const long PS_BS  = (long)NX * PS_LD;
    const long PZ_BS  = (long)NX * PZ_LD;
    const long OUT_BS = (long)256 * NX;
    float* ZTr = ZZ + 256 * ZZ_LD;   // zf_trans rows [256,512)
    float* SE  = CT + 256;           // self_emb cols
    float* XGc = CT + 512;           // xf_g cols

    // 0) prep (xf transpose now folded into the merged conv's A stager)
    round_weights<<<256, 256>>>(Wq, Ws_, Wg, Wfi, WR);
    transpose_round<<<dim3(2, 8, B_), 256>>>(zf, ZFT, NZ);

    // 1) merged conv: A = xf via Tr+cvt (ld=NX); cols 0-255 -> XT (+bq),
    //    cols 256-511 -> xf_g (bn+relu) into CATT cols 512-767
    mm<2,0,5,true,256><<<dim3(4, 8, B_), 256, SMEMB>>>(
        xf, WR, XT, XGc, bq, bg, g_gamma, g_beta, g_mean, g_var,
        NX, 512, NX, 256, XT_LD, CNX, 0, XT_BS, CT_BS);
    // 2) ZZ[512][Nz]: rows<256 zf_g (bn+relu,bg), rows>=256 zf_trans (+bs)
    mm<0,0,4,true,256><<<dim3(1, 4, B_), 256, SMEMB>>>(
        WR + 65536, ZFT, ZZ, nullptr, bg, bs, g_gamma, g_beta, g_mean, g_var,
        512, NZ, 256, 256, ZZ_LD, 0, ZFT_BS, ZZ_BS, 0);
    // 3) PS = XT @ XT^T
    mm<0,0,2,false,256><<<dim3(8, 8, B_), 256, SMEMB>>>(
        XT, XT, PS, nullptr, nullptr, nullptr, nullptr, nullptr, nullptr, nullptr,
        NX, NX, XT_LD, XT_LD, PS_LD, XT_BS, XT_BS, PS_BS, 0);
    // 4) PZ = XT @ zf_trans  (B: Tr from ZTr ld 64)
    mm<0,1,2,false,256><<<dim3(1, 8, B_), 256, SMEMB>>>(
        XT, ZTr, PZ, nullptr, nullptr, nullptr, nullptr, nullptr, nullptr, nullptr,
        NX, NZ, XT_LD, ZZ_LD, PZ_LD, XT_BS, ZZ_BS, PZ_BS, 0);
    // 5) softmax
    softmax_rows<<<dim3(B_ * NX), 256>>>(PS, NX, PS_LD);
    softmax_rows<<<dim3(B_ * NX), 256>>>(PZ, NZ, PZ_LD);
    // 6) self_emb[n][c] = PS @ xf_g^T  (B: Tr from CATT+512 ld 768), K=992
    mm<0,1,2,true,992><<<dim3(2, 8, B_), 256, SMEMB>>>(
        PS, XGc, SE, nullptr, nullptr, nullptr, nullptr, nullptr, nullptr, nullptr,
        NX, 256, PS_LD, CT_LD, CT_LD, PS_BS, CT_BS, CT_BS, 0);
    // 7) emb[n][c] = PZ @ zf_g^T, K=64
    mm<0,0,2,true,64><<<dim3(2, 8, B_), 256, SMEMB>>>(
        PZ, ZZ, CT, nullptr, nullptr, nullptr, nullptr, nullptr, nullptr, nullptr,
        NX, 256, PZ_LD, ZZ_LD, CT_LD, PZ_BS, ZZ_BS, CT_BS, 0);
    // 8) out = relu(bn(Wfi @ CATT^T)), K=768
    mm<0,0,1,false,768><<<dim3(8, 2, B_), 256, SMEMB>>>(
        WR + 196608, CT, out, nullptr, bfi, nullptr, fi_gamma, fi_beta, fi_mean, fi_var,
        256, NX, 768, CT_LD, NX, 0, CT_BS, OUT_BS, 0);
}

// round 12
// speedup vs baseline: 1.0977x; 1.0977x over previous
#include <cuda_runtime.h>
#include <cstdint>

// ---------------------------------------------------------------------------
// Problem constants
// ---------------------------------------------------------------------------
#define B_   32
#define C_   256
#define NX   961
#define NZ   49
#define XT_LD  256
#define ZZ_LD  64
#define CT_LD  768      // CATT row stride
#define CT_ROWS 992     // CATT rows padded (zero rows 961..991)
#define PS_LD  992
#define PZ_LD  64

#define BM 128
#define BK 32
#define AW 4096                 // A tile words (128*32)
#define STW 8192                // words per stage (A+B)
#define SMEMB (3 * STW * 4)     // 96 KB, 3-stage

// ---------------------------------------------------------------------------
// Scratch (device globals; zero-initialized, never freed)
// ---------------------------------------------------------------------------
__device__ float g_XF [(size_t)B_ * NX * 256];        // xf^T   [B][Nx][C] (tf32)
__device__ float g_ZFT[(size_t)B_ * NZ * 256];        // zf^T   [B][Nz][C] (tf32)
__device__ float g_XT [(size_t)B_ * NX * XT_LD];      // xf_trans^T (tf32)
__device__ float g_ZZ [(size_t)B_ * 512 * ZZ_LD];     // [zf_g; zf_trans]
__device__ float g_CT [(size_t)B_ * CT_ROWS * CT_LD]; // [emb|self|xg] n-major
__device__ float g_PS [(size_t)B_ * NX * PS_LD];      // self probs (tf32)
__device__ float g_PZ [(size_t)B_ * NX * PZ_LD];      // cross probs (tf32)
__device__ float g_WR [393216];                       // rounded [Wq|Wg|Ws|Wfi]

// ---------------------------------------------------------------------------
__device__ __forceinline__ uint32_t cvt_tf32(float f) {
    uint32_t r;
    asm("cvt.rna.tf32.f32 %0, %1;" : "=r"(r) : "f"(f));
    return r;
}
__device__ __forceinline__ float round_tf32f(float f) {
    return __uint_as_float(cvt_tf32(f));
}
__device__ __forceinline__ uint32_t smem_u32(const void* p) {
    uint32_t a;
    asm("{ .reg .u64 t; cvta.to.shared.u64 t, %1; cvt.u32.u64 %0, t; }" : "=r"(a) : "l"(p));
    return a;
}
__device__ __forceinline__ void cp16(uint32_t dst, const float* src, int ss) {
    asm volatile("cp.async.cg.shared.global [%0], [%1], 16, %2;"
                 :: "r"(dst), "l"(src), "r"(ss));
}
#define CP_COMMIT() asm volatile("cp.async.commit_group;" ::: "memory")
#define CP_WAIT0()  asm volatile("cp.async.wait_group 0;" ::: "memory")
#define CP_WAIT1()  asm volatile("cp.async.wait_group 1;" ::: "memory")

__device__ __forceinline__ void mma_tf32(float* d, const uint32_t* a, const uint32_t* b) {
    asm volatile(
        "mma.sync.aligned.m16n8k8.row.col.f32.tf32.tf32.f32 "
        "{%0,%1,%2,%3}, {%4,%5,%6,%7}, {%8,%9}, {%0,%1,%2,%3};"
        : "+f"(d[0]), "+f"(d[1]), "+f"(d[2]), "+f"(d[3])
        : "r"(a[0]), "r"(a[1]), "r"(a[2]), "r"(a[3]), "r"(b[0]), "r"(b[1]));
}
__device__ __forceinline__ void ldsm4(uint32_t& r0, uint32_t& r1, uint32_t& r2, uint32_t& r3,
                                      uint32_t addr) {
    asm volatile("ldmatrix.sync.aligned.m8n8.x4.shared.b16 {%0,%1,%2,%3}, [%4];"
                 : "=r"(r0), "=r"(r1), "=r"(r2), "=r"(r3) : "r"(addr));
}

// ---------------------------------------------------------------------------
// Stagers: per-thread state hoisted out of the mainloop.
// Cp: cp.async, src row-major-k (tf32, ld mult of 4, k-tile within row)
// Tr: transpose, src[k][n] tf32: 4 strided (n-coalesced) loads + STS.128
// ---------------------------------------------------------------------------
struct StagerCp {
    const float* p[4];
    uint32_t dst[4];
    int sz[4];
    __device__ __forceinline__ void init(const float* src, int ld, int r0, int rmax, int t) {
#pragma unroll
        for (int i = 0; i < 4; i++) {
            int q = i * 256 + t;
            int row = q >> 3, u = q & 7;
            bool ok = (r0 + row < rmax);
            p[i] = ok ? (src + (size_t)(r0 + row) * ld + u * 4) : src;
            sz[i] = ok ? 16 : 0;
            dst[i] = (uint32_t)(((row << 5) + ((u ^ (row & 7)) << 2)) * 4);
        }
    }
    __device__ __forceinline__ void issue(uint32_t sb) {
#pragma unroll
        for (int i = 0; i < 4; i++) {
            cp16(sb + dst[i], p[i], sz[i]);
            p[i] += BK;
        }
    }
};
struct StagerTr {
    const float* p[4];
    uint32_t dst[4];
    bool ok[4];
    int ld;
    __device__ __forceinline__ void init(const float* src, int ld_, int r0, int rmax, int t) {
        ld = ld_;
#pragma unroll
        for (int i = 0; i < 4; i++) {
            int q = i * 256 + t;
            int lr = q & 127, g = q >> 7;
            int n = r0 + lr;
            ok[i] = (n < rmax);
            p[i] = ok[i] ? (src + (size_t)(g * 4) * ld_ + n) : src;
            dst[i] = (uint32_t)((lr << 5) + ((g ^ (lr & 7)) << 2));
        }
    }
    __device__ __forceinline__ void issue(uint32_t* sw) {
#pragma unroll
        for (int i = 0; i < 4; i++) {
            uint4 w = make_uint4(0u, 0u, 0u, 0u);
            if (ok[i]) {
                const float* s = p[i];
                w.x = __float_as_uint(s[0]);
                w.y = __float_as_uint(s[(size_t)ld]);
                w.z = __float_as_uint(s[(size_t)2 * ld]);
                w.w = __float_as_uint(s[(size_t)3 * ld]);
            }
            *reinterpret_cast<uint4*>(sw + dst[i]) = w;
            p[i] += (size_t)BK * ld;
        }
    }
};

// ---------------------------------------------------------------------------
// tf32 GEMM: D[m][n] = epi( sum_k A[m][k] * B[n][k] ), tile 128x128x32,
// 256 threads, 3-stage cp.async pipeline, LDSM fragments. K compile-time.
// Issue ordering: prefetch-first only when both operands are cp.async;
// Tr-staged operands issue AFTER the compute burst (sync loads must not
// delay the MMA stream).
// EPI 1: relu(bn per row m)
// EPI 2: plain
// EPI 4: Z-stack rows: r<256 relu(bn[r], bias) ; r>=256 +bias2[r-256]
// EPI 5: col split: c<256 +bias[c] -> D ; c>=256 relu(bn[c-256], bias2) -> D2
// ---------------------------------------------------------------------------
template<int LB, int EPI, bool ROUND, int KK>
__global__ void __launch_bounds__(256, 2) mm(
    const float* __restrict__ A, const float* __restrict__ Bm,
    float* __restrict__ D, float* __restrict__ D2,
    const float* __restrict__ bias, const float* __restrict__ bias2,
    const float* __restrict__ gamma, const float* __restrict__ beta,
    const float* __restrict__ mean, const float* __restrict__ var,
    int M, int N, int lda, int ldb, int ldd,
    long abs_, long bbs_, long dbs_, long d2bs_)
{
    constexpr int T = KK / BK;
    constexpr bool PF = (LB == 0);   // prefetch-first only for all-cp.async

    extern __shared__ uint32_t smem[];
    const uint32_t sbyte = smem_u32(smem);

    const int t = threadIdx.x;
    const int wid = t >> 5, lane = t & 31;
    const int warp_m = wid & 3, warp_n = wid >> 2;
    const int qid = lane >> 2, qtid = lane & 3;
    const int b = blockIdx.z;
    const int n0 = blockIdx.x * 128;
    const int m0 = blockIdx.y * BM;

    const float* Ab = A + (long)b * abs_;
    const float* Bb = Bm + (long)b * bbs_;
    float* Db = D + (long)b * dbs_;

    float acc[2][8][4];
#pragma unroll
    for (int i = 0; i < 2; i++)
#pragma unroll
        for (int j = 0; j < 8; j++)
#pragma unroll
            for (int k = 0; k < 4; k++) acc[i][j][k] = 0.f;

    // LDSM per-thread address bases (byte offsets inside a stage's A/B tile).
    const int jm = lane >> 3, r7 = lane & 7;
    const uint32_t aoffb = ((uint32_t)(warp_m * 32 + (jm & 1) * 8 + r7) << 7)
                         + ((uint32_t)(((jm >> 1) ^ (lane & 1))) << 4);
    const uint32_t boffb = ((uint32_t)(warp_n * 64 + (jm >> 1) * 8 + r7) << 7)
                         + ((uint32_t)(((jm & 1) ^ (lane & 1))) << 4);
    const uint32_t rq64 = (uint32_t)(lane & 6) << 4;

    StagerCp sa;
    sa.init(Ab, lda, m0, M, t);
    StagerCp sbC;
    StagerTr sbT;
    if (LB == 0) sbC.init(Bb, ldb, n0, N, t);
    else         sbT.init(Bb, ldb, n0, N, t);

    auto issueStage = [&](int s) {
        sa.issue(sbyte + s * (STW * 4));
        if (LB == 0) sbC.issue(sbyte + s * (STW * 4) + AW * 4);
        else         sbT.issue(smem + s * STW + AW);
        CP_COMMIT();
    };

    // prologue: stages 0 and 1
    issueStage(0);
    if (T > 1) issueStage(1);

    int stg = 0;
#pragma unroll 3
    for (int tt = 0; tt < T; tt++) {
        if (tt + 1 < T) CP_WAIT1(); else CP_WAIT0();
        __syncthreads();

        if (PF && tt + 2 < T) {
            int s2 = stg + 2; if (s2 >= 3) s2 -= 3;
            issueStage(s2);
        }

        const uint32_t sAb = sbyte + (uint32_t)stg * (STW * 4) + aoffb;
        const uint32_t sBb = sbyte + (uint32_t)stg * (STW * 4) + (AW * 4) + boffb;
#pragma unroll
        for (int ks = 0; ks < 4; ks++) {
            const uint32_t tk = ((uint32_t)(32 * ks)) ^ rq64;
            uint32_t afr[2][4];
            ldsm4(afr[0][0], afr[0][1], afr[0][2], afr[0][3], sAb + tk);
            ldsm4(afr[1][0], afr[1][1], afr[1][2], afr[1][3], sAb + tk + 2048);
            uint32_t bfr[8][2];
            ldsm4(bfr[0][0], bfr[0][1], bfr[1][0], bfr[1][1], sBb + tk);
            ldsm4(bfr[2][0], bfr[2][1], bfr[3][0], bfr[3][1], sBb + tk + 2048);
            ldsm4(bfr[4][0], bfr[4][1], bfr[5][0], bfr[5][1], sBb + tk + 4096);
            ldsm4(bfr[6][0], bfr[6][1], bfr[7][0], bfr[7][1], sBb + tk + 6144);
#pragma unroll
            for (int im = 0; im < 2; im++)
#pragma unroll
                for (int jn = 0; jn < 8; jn++)
                    mma_tf32(acc[im][jn], afr[im], bfr[jn]);
        }

        if (!PF && tt + 2 < T) {
            int s2 = stg + 2; if (s2 >= 3) s2 -= 3;
            issueStage(s2);
        }
        stg++; if (stg == 3) stg = 0;
    }

    // ---- epilogue ----
    const int mb = m0 + warp_m * 32;
    const int nb = n0 + warp_n * 64;

    float scl[2][2], sft[2][2];
    if (EPI == 1 || EPI == 4) {
#pragma unroll
        for (int im = 0; im < 2; im++)
#pragma unroll
            for (int h = 0; h < 2; h++) {
                int r = mb + im * 16 + qid + h * 8;
                if (EPI == 1) {
                    int ri = (r < M) ? r : 0;
                    float inv = rsqrtf(var[ri] + 1e-5f);
                    float s = gamma[ri] * inv;
                    scl[im][h] = s;
                    sft[im][h] = (bias[ri] - mean[ri]) * s + beta[ri];
                } else {
                    if (r < 256) {
                        float inv = rsqrtf(var[r] + 1e-5f);
                        float s = gamma[r] * inv;
                        scl[im][h] = s;
                        sft[im][h] = (bias[r] - mean[r]) * s + beta[r];
                    } else {
                        scl[im][h] = 1.f;
                        sft[im][h] = bias2[(r < M) ? (r - 256) : 0];
                    }
                }
            }
    }

    // EPI5: precompute per-column params once (16 columns per thread)
    float cscl[16], csft[16];
    if (EPI == 5) {
#pragma unroll
        for (int jn = 0; jn < 8; jn++)
#pragma unroll
            for (int e = 0; e < 2; e++) {
                int c = nb + jn * 8 + 2 * qtid + e;
                int idx = jn * 2 + e;
                if (c < 256) {
                    cscl[idx] = 1.f;
                    csft[idx] = bias[c];
                } else {
                    int ci = c - 256;
                    float inv = rsqrtf(var[ci] + 1e-5f);
                    float s = gamma[ci] * inv;
                    cscl[idx] = s;
                    csft[idx] = (bias2[ci] - mean[ci]) * s + beta[ci];
                }
            }
    }

    float* D2b = (EPI == 5) ? (D2 + (long)b * d2bs_) : nullptr;

#pragma unroll
    for (int im = 0; im < 2; im++) {
#pragma unroll
        for (int jn = 0; jn < 8; jn++) {
            int c0 = nb + jn * 8 + 2 * qtid;
#pragma unroll
            for (int h = 0; h < 2; h++) {
                int r = mb + im * 16 + qid + h * 8;
                if (r >= M) continue;
                float v0 = acc[im][jn][h * 2 + 0];
                float v1 = acc[im][jn][h * 2 + 1];
                if (EPI == 1) {
                    v0 = fmaxf(v0 * scl[im][h] + sft[im][h], 0.f);
                    v1 = fmaxf(v1 * scl[im][h] + sft[im][h], 0.f);
                }
                if (EPI == 4) {
                    v0 = v0 * scl[im][h] + sft[im][h];
                    v1 = v1 * scl[im][h] + sft[im][h];
                    if (r < 256) { v0 = fmaxf(v0, 0.f); v1 = fmaxf(v1, 0.f); }
                }
                if (EPI == 5) {
#pragma unroll
                    for (int e = 0; e < 2; e++) {
                        int c = c0 + e;
                        int idx = jn * 2 + e;
                        float v = e ? v1 : v0;
                        v = v * cscl[idx] + csft[idx];
                        if (c >= 256) v = fmaxf(v, 0.f);
                        if (ROUND) v = round_tf32f(v);
                        if (c < 256) Db[(long)r * ldd + c] = v;
                        else         D2b[(long)r * CT_LD + (c - 256)] = v;
                    }
                    continue;
                }
                if (ROUND) { v0 = round_tf32f(v0); v1 = round_tf32f(v1); }
                if (c0 < N)     Db[(long)r * ldd + c0]     = v0;
                if (c0 + 1 < N) Db[(long)r * ldd + c0 + 1] = v1;
            }
        }
    }
}

// ---------------------------------------------------------------------------
// Row softmax (row length M <= 1024, padded stride ld); stores tf32-rounded.
// ---------------------------------------------------------------------------
__global__ void softmax_rows(float* __restrict__ L, int M, int ld)
{
    float* p = L + (size_t)blockIdx.x * ld;
    const int t = threadIdx.x;

    float r[4];
    float mx = -1e30f;
#pragma unroll
    for (int i = 0; i < 4; i++) {
        int idx = t + i * 256;
        r[i] = (idx < M) ? p[idx] : -1e30f;
        mx = fmaxf(mx, r[i]);
    }
#pragma unroll
    for (int off = 16; off; off >>= 1)
        mx = fmaxf(mx, __shfl_xor_sync(0xffffffffu, mx, off));

    __shared__ float redmax[8];
    __shared__ float redsum[8];
    if ((t & 31) == 0) redmax[t >> 5] = mx;
    __syncthreads();
    mx = redmax[0];
#pragma unroll
    for (int w = 1; w < 8; w++) mx = fmaxf(mx, redmax[w]);

    float s = 0.f;
#pragma unroll
    for (int i = 0; i < 4; i++) {
        int idx = t + i * 256;
        r[i] = (idx < M) ? __expf(r[i] - mx) : 0.f;
        s += r[i];
    }
#pragma unroll
    for (int off = 16; off; off >>= 1)
        s += __shfl_xor_sync(0xffffffffu, s, off);
    if ((t & 31) == 0) redsum[t >> 5] = s;
    __syncthreads();
    s = 0.f;
#pragma unroll
    for (int w = 0; w < 8; w++) s += redsum[w];

    float inv = 1.f / s;
#pragma unroll
    for (int i = 0; i < 4; i++) {
        int idx = t + i * 256;
        if (idx < M) p[idx] = round_tf32f(r[i] * inv);
    }
}

// ---------------------------------------------------------------------------
// src [B][256][Ns] -> dst [B][Ns][256], tf32-rounded. Dense batch stride.
// ---------------------------------------------------------------------------
__global__ void transpose_round(const float* __restrict__ src, float* __restrict__ dst, int Ns)
{
    __shared__ float tl[32][33];
    const int b = blockIdx.z;
    const int n0 = blockIdx.x * 32, c0 = blockIdx.y * 32;
    const int tx = threadIdx.x & 31, ty = threadIdx.x >> 5;
    const float* s = src + (size_t)b * 256 * Ns;
    float* d = dst + (size_t)b * Ns * 256;
#pragma unroll
    for (int i = 0; i < 4; i++) {
        int c = c0 + ty + i * 8, n = n0 + tx;
        tl[ty + i * 8][tx] = (n < Ns) ? s[(size_t)c * Ns + n] : 0.f;
    }
    __syncthreads();
#pragma unroll
    for (int i = 0; i < 4; i++) {
        int n = n0 + ty + i * 8, c = c0 + tx;
        if (n < Ns) d[(size_t)n * 256 + c] = round_tf32f(tl[tx][ty + i * 8]);
    }
}

// ---------------------------------------------------------------------------
// Pre-round weights into g_WR: [Wq | Wg | Ws | Wfi]
// ---------------------------------------------------------------------------
__global__ void round_weights(const float* __restrict__ wq, const float* __restrict__ ws,
                              const float* __restrict__ wg, const float* __restrict__ wfi,
                              float* __restrict__ o)
{
    for (int i = blockIdx.x * 256 + threadIdx.x; i < 393216; i += gridDim.x * 256) {
        float v;
        if      (i < 65536)  v = wq [i];
        else if (i < 131072) v = wg [i - 65536];
        else if (i < 196608) v = ws [i - 131072];
        else                 v = wfi[i - 196608];
        o[i] = round_tf32f(v);
    }
}

// ---------------------------------------------------------------------------
extern "C" void kernel_launch(void* const* d_in, const int* in_sizes, int n_in,
                              void* d_out, int out_size)
{
    const float* zf  = (const float*)d_in[0];
    const float* xf  = (const float*)d_in[1];
    const float* Wq  = (const float*)d_in[2];
    const float* bq  = (const float*)d_in[3];
    const float* Ws_ = (const float*)d_in[4];
    const float* bs  = (const float*)d_in[5];
    const float* Wg  = (const float*)d_in[6];
    const float* bg  = (const float*)d_in[7];
    const float* g_gamma = (const float*)d_in[8];
    const float* g_beta  = (const float*)d_in[9];
    const float* g_mean  = (const float*)d_in[10];
    const float* g_var   = (const float*)d_in[11];
    const float* Wfi = (const float*)d_in[12];
    const float* bfi = (const float*)d_in[13];
    const float* fi_gamma = (const float*)d_in[14];
    const float* fi_beta  = (const float*)d_in[15];
    const float* fi_mean  = (const float*)d_in[16];
    const float* fi_var   = (const float*)d_in[17];
    float* out = (float*)d_out;

    float *XF, *ZFT, *XT, *ZZ, *CT, *PS, *PZ, *WR;
    cudaGetSymbolAddress((void**)&XF,  g_XF);
    cudaGetSymbolAddress((void**)&ZFT, g_ZFT);
    cudaGetSymbolAddress((void**)&XT,  g_XT);
    cudaGetSymbolAddress((void**)&ZZ,  g_ZZ);
    cudaGetSymbolAddress((void**)&CT,  g_CT);
    cudaGetSymbolAddress((void**)&PS,  g_PS);
    cudaGetSymbolAddress((void**)&PZ,  g_PZ);
    cudaGetSymbolAddress((void**)&WR,  g_WR);

#define SETUP(KER) do { \
    cudaFuncSetAttribute(KER, cudaFuncAttributeMaxDynamicSharedMemorySize, SMEMB); \
    cudaFuncSetAttribute(KER, cudaFuncAttributePreferredSharedMemoryCarveout, 100); \
} while (0)
    SETUP((mm<0,5,true ,256>));
    SETUP((mm<0,4,true ,256>));
    SETUP((mm<0,2,false,256>));
    SETUP((mm<1,2,false,256>));
    SETUP((mm<1,2,true ,992>));
    SETUP((mm<0,2,true ,64 >));
    SETUP((mm<0,1,false,768>));
#undef SETUP

    const long XF_BS  = (long)NX * 256;
    const long ZFT_BS = (long)NZ * 256;
    const long XT_BS  = (long)NX * XT_LD;
    const long ZZ_BS  = (long)512 * ZZ_LD;
    const long CT_BS  = (long)CT_ROWS * CT_LD;
    const long PS_BS  = (long)NX * PS_LD;
    const long PZ_BS  = (long)NX * PZ_LD;
    const long OUT_BS = (long)256 * NX;
    float* ZTr = ZZ + 256 * ZZ_LD;   // zf_trans rows [256,512)
    float* SE  = CT + 256;           // self_emb cols
    float* XGc = CT + 512;           // xf_g cols

    // 0) prep
    round_weights<<<256, 256>>>(Wq, Ws_, Wg, Wfi, WR);
    transpose_round<<<dim3(31, 8, B_), 256>>>(xf, XF, NX);
    transpose_round<<<dim3(2, 8, B_), 256>>>(zf, ZFT, NZ);

    // 1) merged conv: cols 0-255 -> XT (+bq), cols 256-511 -> xf_g (bn+relu)
    mm<0,5,true,256><<<dim3(4, 8, B_), 256, SMEMB>>>(
        XF, WR, XT, XGc, bq, bg, g_gamma, g_beta, g_mean, g_var,
        NX, 512, 256, 256, XT_LD, XF_BS, 0, XT_BS, CT_BS);
    // 2) ZZ[512][Nz]: rows<256 zf_g (bn+relu,bg), rows>=256 zf_trans (+bs)
    mm<0,4,true,256><<<dim3(1, 4, B_), 256, SMEMB>>>(
        WR + 65536, ZFT, ZZ, nullptr, bg, bs, g_gamma, g_beta, g_mean, g_var,
        512, NZ, 256, 256, ZZ_LD, 0, ZFT_BS, ZZ_BS, 0);
    // 3) PS = XT @ XT^T
    mm<0,2,false,256><<<dim3(8, 8, B_), 256, SMEMB>>>(
        XT, XT, PS, nullptr, nullptr, nullptr, nullptr, nullptr, nullptr, nullptr,
        NX, NX, XT_LD, XT_LD, PS_LD, XT_BS, XT_BS, PS_BS, 0);
    // 4) PZ = XT @ zf_trans  (B: Tr from ZTr ld 64)
    mm<1,2,false,256><<<dim3(1, 8, B_), 256, SMEMB>>>(
        XT, ZTr, PZ, nullptr, nullptr, nullptr, nullptr, nullptr, nullptr, nullptr,
        NX, NZ, XT_LD, ZZ_LD, PZ_LD, XT_BS, ZZ_BS, PZ_BS, 0);
    // 5) softmax
    softmax_rows<<<dim3(B_ * NX), 256>>>(PS, NX, PS_LD);
    softmax_rows<<<dim3(B_ * NX), 256>>>(PZ, NZ, PZ_LD);
    // 6) self_emb[n][c] = PS @ xf_g^T  (B: Tr from CATT+512 ld 768), K=992
    mm<1,2,true,992><<<dim3(2, 8, B_), 256, SMEMB>>>(
        PS, XGc, SE, nullptr, nullptr, nullptr, nullptr, nullptr, nullptr, nullptr,
        NX, 256, PS_LD, CT_LD, CT_LD, PS_BS, CT_BS, CT_BS, 0);
    // 7) emb[n][c] = PZ @ zf_g^T, K=64
    mm<0,2,true,64><<<dim3(2, 8, B_), 256, SMEMB>>>(
        PZ, ZZ, CT, nullptr, nullptr, nullptr, nullptr, nullptr, nullptr, nullptr,
        NX, 256, PZ_LD, ZZ_LD, CT_LD, PZ_BS, ZZ_BS, CT_BS, 0);
    // 8) out = relu(bn(Wfi @ CATT^T)), K=768
    mm<0,1,false,768><<<dim3(8, 2, B_), 256, SMEMB>>>(
        WR + 196608, CT, out, nullptr, bfi, nullptr, fi_gamma, fi_beta, fi_mean, fi_var,
        256, NX, 768, CT_LD, NX, 0, CT_BS, OUT_BS, 0);
}

// round 13
// speedup vs baseline: 1.1192x; 1.0197x over previous
#include <cuda_runtime.h>
#include <cstdint>

// ---------------------------------------------------------------------------
// Problem constants
// ---------------------------------------------------------------------------
#define B_   32
#define C_   256
#define NX   961
#define NZ   49
#define XT_LD  256
#define ZG_LD  64
#define CT_LD  768      // CATT row stride
#define CT_ROWS 992     // CATT rows padded (zero rows 961..991)
#define PS_LD  992
#define PZ_LD  64
#define XGT_LD 992      // channel-major xf_g row stride (zero cols 961..991)

#define BM 128
#define BK 32
#define AW 4096                 // A tile words (128*32)
#define STW 8192                // words per stage (A+B)
#define SMEMB (3 * STW * 4)     // 96 KB, 3-stage

// ---------------------------------------------------------------------------
// Scratch (device globals; zero-initialized, never freed)
// ---------------------------------------------------------------------------
__device__ float g_XF [(size_t)B_ * NX * 256];         // xf^T   [B][Nx][C] (tf32)
__device__ float g_ZFT[(size_t)B_ * NZ * 256];         // zf^T   [B][Nz][C] (tf32)
__device__ float g_XT [(size_t)B_ * NX * XT_LD];       // xf_trans^T (tf32)
__device__ float g_ZG [(size_t)B_ * 256 * ZG_LD];      // zf_g  [c][m-pad64]
__device__ float g_ZT2[(size_t)B_ * NZ * 256];         // zf_trans^T [m][c]
__device__ float g_XGT[(size_t)B_ * 256 * XGT_LD];     // xf_g  [c][m-pad992]
__device__ float g_CT [(size_t)B_ * CT_ROWS * CT_LD];  // [emb|self|xg] n-major
__device__ float g_PS [(size_t)B_ * NX * PS_LD];       // self probs (tf32)
__device__ float g_PZ [(size_t)B_ * NX * PZ_LD];       // cross probs (tf32)
__device__ float g_WR [393216];                        // rounded [Wq|Wg|Ws|Wfi]

// ---------------------------------------------------------------------------
__device__ __forceinline__ uint32_t cvt_tf32(float f) {
    uint32_t r;
    asm("cvt.rna.tf32.f32 %0, %1;" : "=r"(r) : "f"(f));
    return r;
}
__device__ __forceinline__ float round_tf32f(float f) {
    return __uint_as_float(cvt_tf32(f));
}
__device__ __forceinline__ uint32_t smem_u32(const void* p) {
    uint32_t a;
    asm("{ .reg .u64 t; cvta.to.shared.u64 t, %1; cvt.u32.u64 %0, t; }" : "=r"(a) : "l"(p));
    return a;
}
__device__ __forceinline__ void cp16(uint32_t dst, const float* src, int ss) {
    asm volatile("cp.async.cg.shared.global [%0], [%1], 16, %2;"
                 :: "r"(dst), "l"(src), "r"(ss));
}
#define CP_COMMIT() asm volatile("cp.async.commit_group;" ::: "memory")
#define CP_WAIT0()  asm volatile("cp.async.wait_group 0;" ::: "memory")
#define CP_WAIT1()  asm volatile("cp.async.wait_group 1;" ::: "memory")

__device__ __forceinline__ void mma_tf32(float* d, const uint32_t* a, const uint32_t* b) {
    asm volatile(
        "mma.sync.aligned.m16n8k8.row.col.f32.tf32.tf32.f32 "
        "{%0,%1,%2,%3}, {%4,%5,%6,%7}, {%8,%9}, {%0,%1,%2,%3};"
        : "+f"(d[0]), "+f"(d[1]), "+f"(d[2]), "+f"(d[3])
        : "r"(a[0]), "r"(a[1]), "r"(a[2]), "r"(a[3]), "r"(b[0]), "r"(b[1]));
}
__device__ __forceinline__ void ldsm4(uint32_t& r0, uint32_t& r1, uint32_t& r2, uint32_t& r3,
                                      uint32_t addr) {
    asm volatile("ldmatrix.sync.aligned.m8n8.x4.shared.b16 {%0,%1,%2,%3}, [%4];"
                 : "=r"(r0), "=r"(r1), "=r"(r2), "=r"(r3) : "r"(addr));
}

// ---------------------------------------------------------------------------
// cp.async stager: src row-major-k (tf32, ld mult of 4, k-tile within row).
// Per-thread state hoisted out of the mainloop.
// ---------------------------------------------------------------------------
struct StagerCp {
    const float* p[4];
    uint32_t dst[4];
    int sz[4];
    __device__ __forceinline__ void init(const float* src, int ld, int r0, int rmax, int t) {
#pragma unroll
        for (int i = 0; i < 4; i++) {
            int q = i * 256 + t;
            int row = q >> 3, u = q & 7;
            bool ok = (r0 + row < rmax);
            p[i] = ok ? (src + (size_t)(r0 + row) * ld + u * 4) : src;
            sz[i] = ok ? 16 : 0;
            dst[i] = (uint32_t)(((row << 5) + ((u ^ (row & 7)) << 2)) * 4);
        }
    }
    __device__ __forceinline__ void issue(uint32_t sb) {
#pragma unroll
        for (int i = 0; i < 4; i++) {
            cp16(sb + dst[i], p[i], sz[i]);
            p[i] += BK;
        }
    }
};

// ---------------------------------------------------------------------------
// tf32 GEMM: D[m][n] = epi( sum_k A[m][k] * B[n][k] ), tile 128x128x32,
// 256 threads, 3-stage all-cp.async prefetch-first pipeline, LDSM fragments.
// K compile-time.
// EPI 1: relu(bn per row m), +ROUND optional
// EPI 2: plain (+ROUND)
// EPI 5: col split: c<256 +bias[c] -> D ; c>=256 relu(bn[c-256], bias2) -> D2
//        (n-major, ld CT_LD) AND (if HAS3) channel-major copy -> D3[c-256][m]
// ---------------------------------------------------------------------------
template<int EPI, bool ROUND, bool HAS3, int KK>
__global__ void __launch_bounds__(256, 2) mm(
    const float* __restrict__ A, const float* __restrict__ Bm,
    float* __restrict__ D, float* __restrict__ D2, float* __restrict__ D3,
    const float* __restrict__ bias, const float* __restrict__ bias2,
    const float* __restrict__ gamma, const float* __restrict__ beta,
    const float* __restrict__ mean, const float* __restrict__ var,
    int M, int N, int lda, int ldb, int ldd,
    long abs_, long bbs_, long dbs_, long d2bs_, long d3bs_)
{
    constexpr int T = KK / BK;

    extern __shared__ uint32_t smem[];
    const uint32_t sbyte = smem_u32(smem);

    const int t = threadIdx.x;
    const int wid = t >> 5, lane = t & 31;
    const int warp_m = wid & 3, warp_n = wid >> 2;
    const int qid = lane >> 2, qtid = lane & 3;
    const int b = blockIdx.z;
    const int n0 = blockIdx.x * 128;
    const int m0 = blockIdx.y * BM;

    const float* Ab = A + (long)b * abs_;
    const float* Bb = Bm + (long)b * bbs_;
    float* Db = D + (long)b * dbs_;

    float acc[2][8][4];
#pragma unroll
    for (int i = 0; i < 2; i++)
#pragma unroll
        for (int j = 0; j < 8; j++)
#pragma unroll
            for (int k = 0; k < 4; k++) acc[i][j][k] = 0.f;

    // LDSM per-thread address bases (byte offsets inside a stage's A/B tile).
    const int jm = lane >> 3, r7 = lane & 7;
    const uint32_t aoffb = ((uint32_t)(warp_m * 32 + (jm & 1) * 8 + r7) << 7)
                         + ((uint32_t)(((jm >> 1) ^ (lane & 1))) << 4);
    const uint32_t boffb = ((uint32_t)(warp_n * 64 + (jm >> 1) * 8 + r7) << 7)
                         + ((uint32_t)(((jm & 1) ^ (lane & 1))) << 4);
    const uint32_t rq64 = (uint32_t)(lane & 6) << 4;

    StagerCp sa, sb;
    sa.init(Ab, lda, m0, M, t);
    sb.init(Bb, ldb, n0, N, t);

    auto issueStage = [&](int s) {
        sa.issue(sbyte + s * (STW * 4));
        sb.issue(sbyte + s * (STW * 4) + AW * 4);
        CP_COMMIT();
    };

    issueStage(0);
    if (T > 1) issueStage(1);

    int stg = 0;
#pragma unroll 3
    for (int tt = 0; tt < T; tt++) {
        if (tt + 1 < T) CP_WAIT1(); else CP_WAIT0();
        __syncthreads();

        if (tt + 2 < T) {
            int s2 = stg + 2; if (s2 >= 3) s2 -= 3;
            issueStage(s2);
        }

        const uint32_t sAb = sbyte + (uint32_t)stg * (STW * 4) + aoffb;
        const uint32_t sBb = sbyte + (uint32_t)stg * (STW * 4) + (AW * 4) + boffb;
#pragma unroll
        for (int ks = 0; ks < 4; ks++) {
            const uint32_t tk = ((uint32_t)(32 * ks)) ^ rq64;
            uint32_t afr[2][4];
            ldsm4(afr[0][0], afr[0][1], afr[0][2], afr[0][3], sAb + tk);
            ldsm4(afr[1][0], afr[1][1], afr[1][2], afr[1][3], sAb + tk + 2048);
            uint32_t bfr[8][2];
            ldsm4(bfr[0][0], bfr[0][1], bfr[1][0], bfr[1][1], sBb + tk);
            ldsm4(bfr[2][0], bfr[2][1], bfr[3][0], bfr[3][1], sBb + tk + 2048);
            ldsm4(bfr[4][0], bfr[4][1], bfr[5][0], bfr[5][1], sBb + tk + 4096);
            ldsm4(bfr[6][0], bfr[6][1], bfr[7][0], bfr[7][1], sBb + tk + 6144);
#pragma unroll
            for (int im = 0; im < 2; im++)
#pragma unroll
                for (int jn = 0; jn < 8; jn++)
                    mma_tf32(acc[im][jn], afr[im], bfr[jn]);
        }
        stg++; if (stg == 3) stg = 0;
    }

    // ---- epilogue ----
    const int mb = m0 + warp_m * 32;
    const int nb = n0 + warp_n * 64;

    float scl[2][2], sft[2][2];
    if (EPI == 1) {
#pragma unroll
        for (int im = 0; im < 2; im++)
#pragma unroll
            for (int h = 0; h < 2; h++) {
                int r = mb + im * 16 + qid + h * 8;
                int ri = (r < M) ? r : 0;
                float inv = rsqrtf(var[ri] + 1e-5f);
                float s = gamma[ri] * inv;
                scl[im][h] = s;
                sft[im][h] = (bias[ri] - mean[ri]) * s + beta[ri];
            }
    }

    // EPI5: precompute per-column params once (16 columns per thread)
    float cscl[16], csft[16];
    if (EPI == 5) {
#pragma unroll
        for (int jn = 0; jn < 8; jn++)
#pragma unroll
            for (int e = 0; e < 2; e++) {
                int c = nb + jn * 8 + 2 * qtid + e;
                int idx = jn * 2 + e;
                if (c < 256) {
                    cscl[idx] = 1.f;
                    csft[idx] = bias[c];
                } else {
                    int ci = c - 256;
                    float inv = rsqrtf(var[ci] + 1e-5f);
                    float s = gamma[ci] * inv;
                    cscl[idx] = s;
                    csft[idx] = (bias2[ci] - mean[ci]) * s + beta[ci];
                }
            }
    }

    float* D2b = (EPI == 5) ? (D2 + (long)b * d2bs_) : nullptr;
    float* D3b = (EPI == 5 && HAS3) ? (D3 + (long)b * d3bs_) : nullptr;

#pragma unroll
    for (int im = 0; im < 2; im++) {
#pragma unroll
        for (int jn = 0; jn < 8; jn++) {
            int c0 = nb + jn * 8 + 2 * qtid;
#pragma unroll
            for (int h = 0; h < 2; h++) {
                int r = mb + im * 16 + qid + h * 8;
                if (r >= M) continue;
                float v0 = acc[im][jn][h * 2 + 0];
                float v1 = acc[im][jn][h * 2 + 1];
                if (EPI == 1) {
                    v0 = fmaxf(v0 * scl[im][h] + sft[im][h], 0.f);
                    v1 = fmaxf(v1 * scl[im][h] + sft[im][h], 0.f);
                }
                if (EPI == 5) {
#pragma unroll
                    for (int e = 0; e < 2; e++) {
                        int c = c0 + e;
                        int idx = jn * 2 + e;
                        float v = e ? v1 : v0;
                        v = v * cscl[idx] + csft[idx];
                        if (c >= 256) v = fmaxf(v, 0.f);
                        if (ROUND) v = round_tf32f(v);
                        if (c < 256) {
                            Db[(long)r * ldd + c] = v;
                        } else {
                            D2b[(long)r * CT_LD + (c - 256)] = v;
                            if (HAS3) D3b[(long)(c - 256) * XGT_LD + r] = v;
                        }
                    }
                    continue;
                }
                if (ROUND) { v0 = round_tf32f(v0); v1 = round_tf32f(v1); }
                if (c0 < N)     Db[(long)r * ldd + c0]     = v0;
                if (c0 + 1 < N) Db[(long)r * ldd + c0 + 1] = v1;
            }
        }
    }
}

// ---------------------------------------------------------------------------
// Row softmax (row length M <= 1024, padded stride ld); stores tf32-rounded.
// ---------------------------------------------------------------------------
__global__ void softmax_rows(float* __restrict__ L, int M, int ld)
{
    float* p = L + (size_t)blockIdx.x * ld;
    const int t = threadIdx.x;

    float r[4];
    float mx = -1e30f;
#pragma unroll
    for (int i = 0; i < 4; i++) {
        int idx = t + i * 256;
        r[i] = (idx < M) ? p[idx] : -1e30f;
        mx = fmaxf(mx, r[i]);
    }
#pragma unroll
    for (int off = 16; off; off >>= 1)
        mx = fmaxf(mx, __shfl_xor_sync(0xffffffffu, mx, off));

    __shared__ float redmax[8];
    __shared__ float redsum[8];
    if ((t & 31) == 0) redmax[t >> 5] = mx;
    __syncthreads();
    mx = redmax[0];
#pragma unroll
    for (int w = 1; w < 8; w++) mx = fmaxf(mx, redmax[w]);

    float s = 0.f;
#pragma unroll
    for (int i = 0; i < 4; i++) {
        int idx = t + i * 256;
        r[i] = (idx < M) ? __expf(r[i] - mx) : 0.f;
        s += r[i];
    }
#pragma unroll
    for (int off = 16; off; off >>= 1)
        s += __shfl_xor_sync(0xffffffffu, s, off);
    if ((t & 31) == 0) redsum[t >> 5] = s;
    __syncthreads();
    s = 0.f;
#pragma unroll
    for (int w = 0; w < 8; w++) s += redsum[w];

    float inv = 1.f / s;
#pragma unroll
    for (int i = 0; i < 4; i++) {
        int idx = t + i * 256;
        if (idx < M) p[idx] = round_tf32f(r[i] * inv);
    }
}

// ---------------------------------------------------------------------------
// src [B][256][Ns] -> dst [B][Ns][256], tf32-rounded. Dense batch stride.
// ---------------------------------------------------------------------------
__global__ void transpose_round(const float* __restrict__ src, float* __restrict__ dst, int Ns)
{
    __shared__ float tl[32][33];
    const int b = blockIdx.z;
    const int n0 = blockIdx.x * 32, c0 = blockIdx.y * 32;
    const int tx = threadIdx.x & 31, ty = threadIdx.x >> 5;
    const float* s = src + (size_t)b * 256 * Ns;
    float* d = dst + (size_t)b * Ns * 256;
#pragma unroll
    for (int i = 0; i < 4; i++) {
        int c = c0 + ty + i * 8, n = n0 + tx;
        tl[ty + i * 8][tx] = (n < Ns) ? s[(size_t)c * Ns + n] : 0.f;
    }
    __syncthreads();
#pragma unroll
    for (int i = 0; i < 4; i++) {
        int n = n0 + ty + i * 8, c = c0 + tx;
        if (n < Ns) d[(size_t)n * 256 + c] = round_tf32f(tl[tx][ty + i * 8]);
    }
}

// ---------------------------------------------------------------------------
// Pre-round weights into g_WR: [Wq | Wg | Ws | Wfi]
// ---------------------------------------------------------------------------
__global__ void round_weights(const float* __restrict__ wq, const float* __restrict__ ws,
                              const float* __restrict__ wg, const float* __restrict__ wfi,
                              float* __restrict__ o)
{
    for (int i = blockIdx.x * 256 + threadIdx.x; i < 393216; i += gridDim.x * 256) {
        float v;
        if      (i < 65536)  v = wq [i];
        else if (i < 131072) v = wg [i - 65536];
        else if (i < 196608) v = ws [i - 131072];
        else                 v = wfi[i - 196608];
        o[i] = round_tf32f(v);
    }
}

// ---------------------------------------------------------------------------
extern "C" void kernel_launch(void* const* d_in, const int* in_sizes, int n_in,
                              void* d_out, int out_size)
{
    const float* zf  = (const float*)d_in[0];
    const float* xf  = (const float*)d_in[1];
    const float* Wq  = (const float*)d_in[2];
    const float* bq  = (const float*)d_in[3];
    const float* Ws_ = (const float*)d_in[4];
    const float* bs  = (const float*)d_in[5];
    const float* Wg  = (const float*)d_in[6];
    const float* bg  = (const float*)d_in[7];
    const float* g_gamma = (const float*)d_in[8];
    const float* g_beta  = (const float*)d_in[9];
    const float* g_mean  = (const float*)d_in[10];
    const float* g_var   = (const float*)d_in[11];
    const float* Wfi = (const float*)d_in[12];
    const float* bfi = (const float*)d_in[13];
    const float* fi_gamma = (const float*)d_in[14];
    const float* fi_beta  = (const float*)d_in[15];
    const float* fi_mean  = (const float*)d_in[16];
    const float* fi_var   = (const float*)d_in[17];
    float* out = (float*)d_out;

    float *XF, *ZFT, *XT, *ZG, *ZT2, *XGT, *CT, *PS, *PZ, *WR;
    cudaGetSymbolAddress((void**)&XF,  g_XF);
    cudaGetSymbolAddress((void**)&ZFT, g_ZFT);
    cudaGetSymbolAddress((void**)&XT,  g_XT);
    cudaGetSymbolAddress((void**)&ZG,  g_ZG);
    cudaGetSymbolAddress((void**)&ZT2, g_ZT2);
    cudaGetSymbolAddress((void**)&XGT, g_XGT);
    cudaGetSymbolAddress((void**)&CT,  g_CT);
    cudaGetSymbolAddress((void**)&PS,  g_PS);
    cudaGetSymbolAddress((void**)&PZ,  g_PZ);
    cudaGetSymbolAddress((void**)&WR,  g_WR);

#define SETUP(KER) do { \
    cudaFuncSetAttribute(KER, cudaFuncAttributeMaxDynamicSharedMemorySize, SMEMB); \
    cudaFuncSetAttribute(KER, cudaFuncAttributePreferredSharedMemoryCarveout, 100); \
} while (0)
    SETUP((mm<5,true ,true ,256>));
    SETUP((mm<5,true ,false,256>));
    SETUP((mm<1,true ,false,256>));
    SETUP((mm<2,false,false,256>));
    SETUP((mm<2,true ,false,992>));
    SETUP((mm<2,true ,false,64 >));
    SETUP((mm<1,false,false,768>));
#undef SETUP

    const long XF_BS  = (long)NX * 256;
    const long ZFT_BS = (long)NZ * 256;
    const long XT_BS  = (long)NX * XT_LD;
    const long ZG_BS  = (long)256 * ZG_LD;
    const long ZT2_BS = (long)NZ * 256;
    const long XGT_BS = (long)256 * XGT_LD;
    const long CT_BS  = (long)CT_ROWS * CT_LD;
    const long PS_BS  = (long)NX * PS_LD;
    const long PZ_BS  = (long)NX * PZ_LD;
    const long OUT_BS = (long)256 * NX;
    float* SE  = CT + 256;           // self_emb cols
    float* XGc = CT + 512;           // xf_g cols

    // 0) prep
    round_weights<<<256, 256>>>(Wq, Ws_, Wg, Wfi, WR);
    transpose_round<<<dim3(31, 8, B_), 256>>>(xf, XF, NX);
    transpose_round<<<dim3(2, 8, B_), 256>>>(zf, ZFT, NZ);

    // 1) merged conv: cols 0-255 -> XT (+bq); cols 256-511 -> xf_g (bn+relu)
    //    into CATT cols 512-767 AND channel-major XGT
    mm<5,true,true,256><<<dim3(4, 8, B_), 256, SMEMB>>>(
        XF, WR, XT, XGc, XGT, bq, bg, g_gamma, g_beta, g_mean, g_var,
        NX, 512, 256, 256, XT_LD, XF_BS, 0, XT_BS, CT_BS, XGT_BS);
    // 2) zf_g[c][m] = relu(bn(Wg @ zf))  (A=Wg rows, B=ZFT)
    mm<1,true,false,256><<<dim3(1, 2, B_), 256, SMEMB>>>(
        WR + 65536, ZFT, ZG, nullptr, nullptr, bg, nullptr,
        g_gamma, g_beta, g_mean, g_var,
        256, NZ, 256, 256, ZG_LD, 0, ZFT_BS, ZG_BS, 0, 0);
    // 3) zf_trans^T[m][c] = zf^T @ Ws^T + bs  (EPI5, all cols < 256 -> +bias)
    mm<5,true,false,256><<<dim3(2, 1, B_), 256, SMEMB>>>(
        ZFT, WR + 131072, ZT2, ZT2, ZT2, bs, nullptr,
        nullptr, nullptr, nullptr, nullptr,
        NZ, 256, 256, 256, 256, ZFT_BS, 0, ZT2_BS, 0, 0);
    // 4) PS = XT @ XT^T
    mm<2,false,false,256><<<dim3(8, 8, B_), 256, SMEMB>>>(
        XT, XT, PS, nullptr, nullptr, nullptr, nullptr, nullptr, nullptr,
        nullptr, nullptr,
        NX, NX, XT_LD, XT_LD, PS_LD, XT_BS, XT_BS, PS_BS, 0, 0);
    // 5) PZ = XT @ ZT2^T   (B = ZT2 rows [m][c], cp.async)
    mm<2,false,false,256><<<dim3(1, 8, B_), 256, SMEMB>>>(
        XT, ZT2, PZ, nullptr, nullptr, nullptr, nullptr, nullptr, nullptr,
        nullptr, nullptr,
        NX, NZ, XT_LD, 256, PZ_LD, XT_BS, ZT2_BS, PZ_BS, 0, 0);
    // 6) softmax
    softmax_rows<<<dim3(B_ * NX), 256>>>(PS, NX, PS_LD);
    softmax_rows<<<dim3(B_ * NX), 256>>>(PZ, NZ, PZ_LD);
    // 7) self_emb[n][c] = PS @ XGT^T  (B = XGT rows [c][m-pad992], cp.async), K=992
    mm<2,true,false,992><<<dim3(2, 8, B_), 256, SMEMB>>>(
        PS, XGT, SE, nullptr, nullptr, nullptr, nullptr, nullptr, nullptr,
        nullptr, nullptr,
        NX, 256, PS_LD, XGT_LD, CT_LD, PS_BS, XGT_BS, CT_BS, 0, 0);
    // 8) emb[n][c] = PZ @ zf_g^T, K=64
    mm<2,true,false,64><<<dim3(2, 8, B_), 256, SMEMB>>>(
        PZ, ZG, CT, nullptr, nullptr, nullptr, nullptr, nullptr, nullptr,
        nullptr, nullptr,
        NX, 256, PZ_LD, ZG_LD, CT_LD, PZ_BS, ZG_BS, CT_BS, 0, 0);
    // 9) out = relu(bn(Wfi @ CATT^T)), K=768
    mm<1,false,false,768><<<dim3(8, 2, B_), 256, SMEMB>>>(
        WR + 196608, CT, out, nullptr, nullptr, bfi, nullptr,
        fi_gamma, fi_beta, fi_mean, fi_var,
        256, NX, 768, CT_LD, NX, 0, CT_BS, OUT_BS, 0, 0);
}

// round 14
// speedup vs baseline: 1.1899x; 1.0631x over previous
#include <cuda_runtime.h>
#include <cstdint>

// ---------------------------------------------------------------------------
// Problem constants
// ---------------------------------------------------------------------------
#define B_   32
#define C_   256
#define NX   961
#define NZ   49
#define XTZ_ROWS 1024   // rows 0..960 = xf_trans^T, 961..1009 = zf_trans^T, rest 0
#define ZG_LD  64
#define CT_LD  768      // CATT row stride
#define CT_ROWS 992     // CATT rows padded (zero rows 961..991)
#define PS_LD  1056     // cols 0..960 self logits/probs, 992..1040 cross, rest 0
#define XGT_LD 992      // channel-major xf_g row stride (zero cols 961..991)

#define BM 128
#define BK 32
#define AW 4096                 // A tile words (128*32)
#define STW 8192                // words per stage (A+B)
#define SMEMB (3 * STW * 4)     // 96 KB, 3-stage

// ---------------------------------------------------------------------------
// Scratch (device globals; zero-initialized, never freed)
// ---------------------------------------------------------------------------
__device__ float g_XF [(size_t)B_ * NX * 256];          // xf^T   [B][Nx][C] (tf32)
__device__ float g_ZFT[(size_t)B_ * NZ * 256];          // zf^T   [B][Nz][C] (tf32)
__device__ float g_XTZ[(size_t)B_ * XTZ_ROWS * 256];    // [xf_trans^T; zf_trans^T]
__device__ float g_ZG [(size_t)B_ * 256 * ZG_LD];       // zf_g  [c][m-pad64]
__device__ float g_XGT[(size_t)B_ * 256 * XGT_LD];      // xf_g  [c][m-pad992]
__device__ float g_CT [(size_t)B_ * CT_ROWS * CT_LD];   // [emb|self|xg] n-major
__device__ float g_PS [(size_t)B_ * NX * PS_LD];        // probs: self + cross
__device__ float g_WR [393216];                         // rounded [Wq|Wg|Ws|Wfi]

// ---------------------------------------------------------------------------
__device__ __forceinline__ uint32_t cvt_tf32(float f) {
    uint32_t r;
    asm("cvt.rna.tf32.f32 %0, %1;" : "=r"(r) : "f"(f));
    return r;
}
__device__ __forceinline__ float round_tf32f(float f) {
    return __uint_as_float(cvt_tf32(f));
}
__device__ __forceinline__ uint32_t smem_u32(const void* p) {
    uint32_t a;
    asm("{ .reg .u64 t; cvta.to.shared.u64 t, %1; cvt.u32.u64 %0, t; }" : "=r"(a) : "l"(p));
    return a;
}
__device__ __forceinline__ void cp16(uint32_t dst, const float* src, int ss) {
    asm volatile("cp.async.cg.shared.global [%0], [%1], 16, %2;"
                 :: "r"(dst), "l"(src), "r"(ss));
}
#define CP_COMMIT() asm volatile("cp.async.commit_group;" ::: "memory")
#define CP_WAIT0()  asm volatile("cp.async.wait_group 0;" ::: "memory")
#define CP_WAIT1()  asm volatile("cp.async.wait_group 1;" ::: "memory")

__device__ __forceinline__ void mma_tf32(float* d, const uint32_t* a, const uint32_t* b) {
    asm volatile(
        "mma.sync.aligned.m16n8k8.row.col.f32.tf32.tf32.f32 "
        "{%0,%1,%2,%3}, {%4,%5,%6,%7}, {%8,%9}, {%0,%1,%2,%3};"
        : "+f"(d[0]), "+f"(d[1]), "+f"(d[2]), "+f"(d[3])
        : "r"(a[0]), "r"(a[1]), "r"(a[2]), "r"(a[3]), "r"(b[0]), "r"(b[1]));
}
__device__ __forceinline__ void ldsm4(uint32_t& r0, uint32_t& r1, uint32_t& r2, uint32_t& r3,
                                      uint32_t addr) {
    asm volatile("ldmatrix.sync.aligned.m8n8.x4.shared.b16 {%0,%1,%2,%3}, [%4];"
                 : "=r"(r0), "=r"(r1), "=r"(r2), "=r"(r3) : "r"(addr));
}

// ---------------------------------------------------------------------------
// cp.async stager: src row-major-k (tf32, ld mult of 4, k-tile within row).
// ---------------------------------------------------------------------------
struct StagerCp {
    const float* p[4];
    uint32_t dst[4];
    int sz[4];
    __device__ __forceinline__ void init(const float* src, int ld, int r0, int rmax, int t) {
#pragma unroll
        for (int i = 0; i < 4; i++) {
            int q = i * 256 + t;
            int row = q >> 3, u = q & 7;
            bool ok = (r0 + row < rmax);
            p[i] = ok ? (src + (size_t)(r0 + row) * ld + u * 4) : src;
            sz[i] = ok ? 16 : 0;
            dst[i] = (uint32_t)(((row << 5) + ((u ^ (row & 7)) << 2)) * 4);
        }
    }
    __device__ __forceinline__ void issue(uint32_t sb) {
#pragma unroll
        for (int i = 0; i < 4; i++) {
            cp16(sb + dst[i], p[i], sz[i]);
            p[i] += BK;
        }
    }
};

// ---------------------------------------------------------------------------
// tf32 GEMM: D[m][n] = epi( sum_k A[m][k] * B[n][k] ), tile 128x128x32,
// 256 threads, 3-stage all-cp.async prefetch-first pipeline, LDSM fragments.
// K compile-time.
// EPI 1: relu(bn per row m), +ROUND optional
// EPI 2: plain (+ROUND)
// EPI 5: col split: c<256 +bias[c] -> D ; c>=256 relu(bn[c-256], bias2) -> D2
//        (n-major, ld CT_LD) AND (if HAS3) channel-major copy -> D3[c-256][m]
// EPI 6: merged logits: c<961 -> D[r][c]; 961<=c<1010 -> D[r][c+31]
// ---------------------------------------------------------------------------
template<int EPI, bool ROUND, bool HAS3, int KK>
__global__ void __launch_bounds__(256, 2) mm(
    const float* __restrict__ A, const float* __restrict__ Bm,
    float* __restrict__ D, float* __restrict__ D2, float* __restrict__ D3,
    const float* __restrict__ bias, const float* __restrict__ bias2,
    const float* __restrict__ gamma, const float* __restrict__ beta,
    const float* __restrict__ mean, const float* __restrict__ var,
    int M, int N, int lda, int ldb, int ldd,
    long abs_, long bbs_, long dbs_, long d2bs_, long d3bs_)
{
    constexpr int T = KK / BK;

    extern __shared__ uint32_t smem[];
    const uint32_t sbyte = smem_u32(smem);

    const int t = threadIdx.x;
    const int wid = t >> 5, lane = t & 31;
    const int warp_m = wid & 3, warp_n = wid >> 2;
    const int qid = lane >> 2, qtid = lane & 3;
    const int b = blockIdx.z;
    const int n0 = blockIdx.x * 128;
    const int m0 = blockIdx.y * BM;

    const float* Ab = A + (long)b * abs_;
    const float* Bb = Bm + (long)b * bbs_;
    float* Db = D + (long)b * dbs_;

    float acc[2][8][4];
#pragma unroll
    for (int i = 0; i < 2; i++)
#pragma unroll
        for (int j = 0; j < 8; j++)
#pragma unroll
            for (int k = 0; k < 4; k++) acc[i][j][k] = 0.f;

    // LDSM per-thread address bases (byte offsets inside a stage's A/B tile).
    const int jm = lane >> 3, r7 = lane & 7;
    const uint32_t aoffb = ((uint32_t)(warp_m * 32 + (jm & 1) * 8 + r7) << 7)
                         + ((uint32_t)(((jm >> 1) ^ (lane & 1))) << 4);
    const uint32_t boffb = ((uint32_t)(warp_n * 64 + (jm >> 1) * 8 + r7) << 7)
                         + ((uint32_t)(((jm & 1) ^ (lane & 1))) << 4);
    const uint32_t rq64 = (uint32_t)(lane & 6) << 4;

    StagerCp sa, sb;
    sa.init(Ab, lda, m0, M, t);
    sb.init(Bb, ldb, n0, N, t);

    auto issueStage = [&](int s) {
        sa.issue(sbyte + s * (STW * 4));
        sb.issue(sbyte + s * (STW * 4) + AW * 4);
        CP_COMMIT();
    };

    issueStage(0);
    if (T > 1) issueStage(1);

    int stg = 0;
#pragma unroll 3
    for (int tt = 0; tt < T; tt++) {
        if (tt + 1 < T) CP_WAIT1(); else CP_WAIT0();
        __syncthreads();

        if (tt + 2 < T) {
            int s2 = stg + 2; if (s2 >= 3) s2 -= 3;
            issueStage(s2);
        }

        const uint32_t sAb = sbyte + (uint32_t)stg * (STW * 4) + aoffb;
        const uint32_t sBb = sbyte + (uint32_t)stg * (STW * 4) + (AW * 4) + boffb;
#pragma unroll
        for (int ks = 0; ks < 4; ks++) {
            const uint32_t tk = ((uint32_t)(32 * ks)) ^ rq64;
            uint32_t afr[2][4];
            ldsm4(afr[0][0], afr[0][1], afr[0][2], afr[0][3], sAb + tk);
            ldsm4(afr[1][0], afr[1][1], afr[1][2], afr[1][3], sAb + tk + 2048);
            uint32_t bfr[8][2];
            ldsm4(bfr[0][0], bfr[0][1], bfr[1][0], bfr[1][1], sBb + tk);
            ldsm4(bfr[2][0], bfr[2][1], bfr[3][0], bfr[3][1], sBb + tk + 2048);
            ldsm4(bfr[4][0], bfr[4][1], bfr[5][0], bfr[5][1], sBb + tk + 4096);
            ldsm4(bfr[6][0], bfr[6][1], bfr[7][0], bfr[7][1], sBb + tk + 6144);
#pragma unroll
            for (int im = 0; im < 2; im++)
#pragma unroll
                for (int jn = 0; jn < 8; jn++)
                    mma_tf32(acc[im][jn], afr[im], bfr[jn]);
        }
        stg++; if (stg == 3) stg = 0;
    }

    // ---- epilogue ----
    const int mb = m0 + warp_m * 32;
    const int nb = n0 + warp_n * 64;

    float scl[2][2], sft[2][2];
    if (EPI == 1) {
#pragma unroll
        for (int im = 0; im < 2; im++)
#pragma unroll
            for (int h = 0; h < 2; h++) {
                int r = mb + im * 16 + qid + h * 8;
                int ri = (r < M) ? r : 0;
                float inv = rsqrtf(var[ri] + 1e-5f);
                float s = gamma[ri] * inv;
                scl[im][h] = s;
                sft[im][h] = (bias[ri] - mean[ri]) * s + beta[ri];
            }
    }

    // EPI5: precompute per-column params once (16 columns per thread)
    float cscl[16], csft[16];
    if (EPI == 5) {
#pragma unroll
        for (int jn = 0; jn < 8; jn++)
#pragma unroll
            for (int e = 0; e < 2; e++) {
                int c = nb + jn * 8 + 2 * qtid + e;
                int idx = jn * 2 + e;
                if (c < 256) {
                    cscl[idx] = 1.f;
                    csft[idx] = bias[c];
                } else {
                    int ci = c - 256;
                    float inv = rsqrtf(var[ci] + 1e-5f);
                    float s = gamma[ci] * inv;
                    cscl[idx] = s;
                    csft[idx] = (bias2[ci] - mean[ci]) * s + beta[ci];
                }
            }
    }

    float* D2b = (EPI == 5) ? (D2 + (long)b * d2bs_) : nullptr;
    float* D3b = (EPI == 5 && HAS3) ? (D3 + (long)b * d3bs_) : nullptr;

#pragma unroll
    for (int im = 0; im < 2; im++) {
#pragma unroll
        for (int jn = 0; jn < 8; jn++) {
            int c0 = nb + jn * 8 + 2 * qtid;
#pragma unroll
            for (int h = 0; h < 2; h++) {
                int r = mb + im * 16 + qid + h * 8;
                if (r >= M) continue;
                float v0 = acc[im][jn][h * 2 + 0];
                float v1 = acc[im][jn][h * 2 + 1];
                if (EPI == 1) {
                    v0 = fmaxf(v0 * scl[im][h] + sft[im][h], 0.f);
                    v1 = fmaxf(v1 * scl[im][h] + sft[im][h], 0.f);
                }
                if (EPI == 5) {
#pragma unroll
                    for (int e = 0; e < 2; e++) {
                        int c = c0 + e;
                        int idx = jn * 2 + e;
                        float v = e ? v1 : v0;
                        v = v * cscl[idx] + csft[idx];
                        if (c >= 256) v = fmaxf(v, 0.f);
                        if (ROUND) v = round_tf32f(v);
                        if (c < 256) {
                            Db[(long)r * ldd + c] = v;
                        } else {
                            D2b[(long)r * CT_LD + (c - 256)] = v;
                            if (HAS3) D3b[(long)(c - 256) * XGT_LD + r] = v;
                        }
                    }
                    continue;
                }
                if (EPI == 6) {
#pragma unroll
                    for (int e = 0; e < 2; e++) {
                        int c = c0 + e;
                        float v = e ? v1 : v0;
                        if (c < 1010) {
                            int dc = (c < 961) ? c : (c + 31);   // cross keys -> cols 992+
                            Db[(long)r * ldd + dc] = v;
                        }
                    }
                    continue;
                }
                if (ROUND) { v0 = round_tf32f(v0); v1 = round_tf32f(v1); }
                if (c0 < N)     Db[(long)r * ldd + c0]     = v0;
                if (c0 + 1 < N) Db[(long)r * ldd + c0 + 1] = v1;
            }
        }
    }
}

// ---------------------------------------------------------------------------
// Dual-segment row softmax over PS rows (ld PS_LD):
//   seg1: cols [0, 961)   (self attention)
//   seg2: cols [992, 1041) (cross attention, 49 keys)
// Stores tf32-rounded.
// ---------------------------------------------------------------------------
__global__ void softmax_rows2(float* __restrict__ L)
{
    float* p = L + (size_t)blockIdx.x * PS_LD;
    const int t = threadIdx.x;

    __shared__ float redmax[8];
    __shared__ float redsum[8];

    // ---- segment 1: M = 961 ----
    {
        float r[4];
        float mx = -1e30f;
#pragma unroll
        for (int i = 0; i < 4; i++) {
            int idx = t + i * 256;
            r[i] = (idx < NX) ? p[idx] : -1e30f;
            mx = fmaxf(mx, r[i]);
        }
#pragma unroll
        for (int off = 16; off; off >>= 1)
            mx = fmaxf(mx, __shfl_xor_sync(0xffffffffu, mx, off));
        if ((t & 31) == 0) redmax[t >> 5] = mx;
        __syncthreads();
        mx = redmax[0];
#pragma unroll
        for (int w = 1; w < 8; w++) mx = fmaxf(mx, redmax[w]);

        float s = 0.f;
#pragma unroll
        for (int i = 0; i < 4; i++) {
            int idx = t + i * 256;
            r[i] = (idx < NX) ? __expf(r[i] - mx) : 0.f;
            s += r[i];
        }
#pragma unroll
        for (int off = 16; off; off >>= 1)
            s += __shfl_xor_sync(0xffffffffu, s, off);
        if ((t & 31) == 0) redsum[t >> 5] = s;
        __syncthreads();
        s = 0.f;
#pragma unroll
        for (int w = 0; w < 8; w++) s += redsum[w];

        float inv = 1.f / s;
#pragma unroll
        for (int i = 0; i < 4; i++) {
            int idx = t + i * 256;
            if (idx < NX) p[idx] = round_tf32f(r[i] * inv);
        }
    }
    __syncthreads();

    // ---- segment 2: 49 cross keys at cols 992.. ----
    {
        float v = (t < NZ) ? p[992 + t] : -1e30f;
        float mx = v;
#pragma unroll
        for (int off = 16; off; off >>= 1)
            mx = fmaxf(mx, __shfl_xor_sync(0xffffffffu, mx, off));
        if ((t & 31) == 0) redmax[t >> 5] = mx;
        __syncthreads();
        mx = redmax[0];
#pragma unroll
        for (int w = 1; w < 8; w++) mx = fmaxf(mx, redmax[w]);

        float ev = (t < NZ) ? __expf(v - mx) : 0.f;
        float s = ev;
#pragma unroll
        for (int off = 16; off; off >>= 1)
            s += __shfl_xor_sync(0xffffffffu, s, off);
        if ((t & 31) == 0) redsum[t >> 5] = s;
        __syncthreads();
        s = 0.f;
#pragma unroll
        for (int w = 0; w < 8; w++) s += redsum[w];

        if (t < NZ) p[992 + t] = round_tf32f(ev * (1.f / s));
    }
}

// ---------------------------------------------------------------------------
// src [B][256][Ns] -> dst [B][Ns][256], tf32-rounded. Dense batch stride.
// ---------------------------------------------------------------------------
__global__ void transpose_round(const float* __restrict__ src, float* __restrict__ dst, int Ns)
{
    __shared__ float tl[32][33];
    const int b = blockIdx.z;
    const int n0 = blockIdx.x * 32, c0 = blockIdx.y * 32;
    const int tx = threadIdx.x & 31, ty = threadIdx.x >> 5;
    const float* s = src + (size_t)b * 256 * Ns;
    float* d = dst + (size_t)b * Ns * 256;
#pragma unroll
    for (int i = 0; i < 4; i++) {
        int c = c0 + ty + i * 8, n = n0 + tx;
        tl[ty + i * 8][tx] = (n < Ns) ? s[(size_t)c * Ns + n] : 0.f;
    }
    __syncthreads();
#pragma unroll
    for (int i = 0; i < 4; i++) {
        int n = n0 + ty + i * 8, c = c0 + tx;
        if (n < Ns) d[(size_t)n * 256 + c] = round_tf32f(tl[tx][ty + i * 8]);
    }
}

// ---------------------------------------------------------------------------
// Pre-round weights into g_WR: [Wq | Wg | Ws | Wfi]
// ---------------------------------------------------------------------------
__global__ void round_weights(const float* __restrict__ wq, const float* __restrict__ ws,
                              const float* __restrict__ wg, const float* __restrict__ wfi,
                              float* __restrict__ o)
{
    for (int i = blockIdx.x * 256 + threadIdx.x; i < 393216; i += gridDim.x * 256) {
        float v;
        if      (i < 65536)  v = wq [i];
        else if (i < 131072) v = wg [i - 65536];
        else if (i < 196608) v = ws [i - 131072];
        else                 v = wfi[i - 196608];
        o[i] = round_tf32f(v);
    }
}

// ---------------------------------------------------------------------------
extern "C" void kernel_launch(void* const* d_in, const int* in_sizes, int n_in,
                              void* d_out, int out_size)
{
    const float* zf  = (const float*)d_in[0];
    const float* xf  = (const float*)d_in[1];
    const float* Wq  = (const float*)d_in[2];
    const float* bq  = (const float*)d_in[3];
    const float* Ws_ = (const float*)d_in[4];
    const float* bs  = (const float*)d_in[5];
    const float* Wg  = (const float*)d_in[6];
    const float* bg  = (const float*)d_in[7];
    const float* g_gamma = (const float*)d_in[8];
    const float* g_beta  = (const float*)d_in[9];
    const float* g_mean  = (const float*)d_in[10];
    const float* g_var   = (const float*)d_in[11];
    const float* Wfi = (const float*)d_in[12];
    const float* bfi = (const float*)d_in[13];
    const float* fi_gamma = (const float*)d_in[14];
    const float* fi_beta  = (const float*)d_in[15];
    const float* fi_mean  = (const float*)d_in[16];
    const float* fi_var   = (const float*)d_in[17];
    float* out = (float*)d_out;

    float *XF, *ZFT, *XTZ, *ZG, *XGT, *CT, *PS, *WR;
    cudaGetSymbolAddress((void**)&XF,  g_XF);
    cudaGetSymbolAddress((void**)&ZFT, g_ZFT);
    cudaGetSymbolAddress((void**)&XTZ, g_XTZ);
    cudaGetSymbolAddress((void**)&ZG,  g_ZG);
    cudaGetSymbolAddress((void**)&XGT, g_XGT);
    cudaGetSymbolAddress((void**)&CT,  g_CT);
    cudaGetSymbolAddress((void**)&PS,  g_PS);
    cudaGetSymbolAddress((void**)&WR,  g_WR);

#define SETUP(KER) do { \
    cudaFuncSetAttribute(KER, cudaFuncAttributeMaxDynamicSharedMemorySize, SMEMB); \
    cudaFuncSetAttribute(KER, cudaFuncAttributePreferredSharedMemoryCarveout, 100); \
} while (0)
    SETUP((mm<5,true ,true ,256>));
    SETUP((mm<1,true ,false,256>));
    SETUP((mm<5,true ,false,256>));
    SETUP((mm<6,false,false,256>));
    SETUP((mm<2,true ,false,992>));
    SETUP((mm<2,true ,false,64 >));
    SETUP((mm<1,false,false,768>));
#undef SETUP

    const long XF_BS  = (long)NX * 256;
    const long ZFT_BS = (long)NZ * 256;
    const long XTZ_BS = (long)XTZ_ROWS * 256;
    const long ZG_BS  = (long)256 * ZG_LD;
    const long XGT_BS = (long)256 * XGT_LD;
    const long CT_BS  = (long)CT_ROWS * CT_LD;
    const long PS_BS  = (long)NX * PS_LD;
    const long OUT_BS = (long)256 * NX;
    float* SE  = CT + 256;             // self_emb cols
    float* XGc = CT + 512;             // xf_g cols
    float* ZT2 = XTZ + 961 * 256;      // zf_trans^T rows inside XTZ

    // 0) prep
    round_weights<<<256, 256>>>(Wq, Ws_, Wg, Wfi, WR);
    transpose_round<<<dim3(31, 8, B_), 256>>>(xf, XF, NX);
    transpose_round<<<dim3(2, 8, B_), 256>>>(zf, ZFT, NZ);

    // 1) merged conv: cols 0-255 -> XTZ rows 0..960 (+bq);
    //    cols 256-511 -> xf_g (bn+relu) into CATT cols 512-767 AND XGT
    mm<5,true,true,256><<<dim3(4, 8, B_), 256, SMEMB>>>(
        XF, WR, XTZ, XGc, XGT, bq, bg, g_gamma, g_beta, g_mean, g_var,
        NX, 512, 256, 256, 256, XF_BS, 0, XTZ_BS, CT_BS, XGT_BS);
    // 2) zf_g[c][m] = relu(bn(Wg @ zf))
    mm<1,true,false,256><<<dim3(1, 2, B_), 256, SMEMB>>>(
        WR + 65536, ZFT, ZG, nullptr, nullptr, bg, nullptr,
        g_gamma, g_beta, g_mean, g_var,
        256, NZ, 256, 256, ZG_LD, 0, ZFT_BS, ZG_BS, 0, 0);
    // 3) zf_trans^T[m][c] = zf^T @ Ws^T + bs  -> XTZ rows 961..1009
    mm<5,true,false,256><<<dim3(2, 1, B_), 256, SMEMB>>>(
        ZFT, WR + 131072, ZT2, ZT2, ZT2, bs, nullptr,
        nullptr, nullptr, nullptr, nullptr,
        NZ, 256, 256, 256, 256, ZFT_BS, 0, XTZ_BS, 0, 0);
    // 4) merged logits: Q = XTZ rows 0..960, keys = XTZ rows 0..1009.
    //    cols <961 -> PS self; 961..1009 -> PS cols 992.. (cross)
    mm<6,false,false,256><<<dim3(8, 8, B_), 256, SMEMB>>>(
        XTZ, XTZ, PS, nullptr, nullptr, nullptr, nullptr, nullptr, nullptr,
        nullptr, nullptr,
        NX, 1010, 256, 256, PS_LD, XTZ_BS, XTZ_BS, PS_BS, 0, 0);
    // 5) dual-segment softmax (self + cross in one launch)
    softmax_rows2<<<dim3(B_ * NX), 256>>>(PS);
    // 6) self_emb[n][c] = PS @ XGT^T, K=992
    mm<2,true,false,992><<<dim3(2, 8, B_), 256, SMEMB>>>(
        PS, XGT, SE, nullptr, nullptr, nullptr, nullptr, nullptr, nullptr,
        nullptr, nullptr,
        NX, 256, PS_LD, XGT_LD, CT_LD, PS_BS, XGT_BS, CT_BS, 0, 0);
    // 7) emb[n][c] = PZ @ zf_g^T  (A = PS cols 992.., ld PS_LD), K=64
    mm<2,true,false,64><<<dim3(2, 8, B_), 256, SMEMB>>>(
        PS + 992, ZG, CT, nullptr, nullptr, nullptr, nullptr, nullptr, nullptr,
        nullptr, nullptr,
        NX, 256, PS_LD, ZG_LD, CT_LD, PS_BS, ZG_BS, CT_BS, 0, 0);
    // 8) out = relu(bn(Wfi @ CATT^T)), K=768
    mm<1,false,false,768><<<dim3(8, 2, B_), 256, SMEMB>>>(
        WR + 196608, CT, out, nullptr, nullptr, bfi, nullptr,
        fi_gamma, fi_beta, fi_mean, fi_var,
        256, NX, 768, CT_LD, NX, 0, CT_BS, OUT_BS, 0, 0);
}

// round 16
// speedup vs baseline: 1.2042x; 1.0120x over previous
#include <cuda_runtime.h>
#include <cstdint>

// ---------------------------------------------------------------------------
// Problem constants
// ---------------------------------------------------------------------------
#define B_   32
#define C_   256
#define NX   961
#define NZ   49
#define XTZ_ROWS 1024   // rows 0..960 = xf_trans^T, 961..1009 = zf_trans^T, rest 0
#define ZG_LD  64
#define CT_LD  768      // CATT row stride
#define CT_ROWS 992     // CATT rows padded (zero rows 961..991)
#define PS_LD  1056     // cols 0..960 self logits/probs, 992..1040 cross, rest 0
#define XGT_LD 992      // channel-major xf_g row stride (zero cols 961..991)

#define BM 128
#define BK 32
#define AW 4096                 // A tile words (128*32)
#define STW 8192                // words per stage (A+B)
#define SMEMB (3 * STW * 4)     // 96 KB, 3-stage

// ---------------------------------------------------------------------------
// Scratch (device globals; zero-initialized, never freed)
// ---------------------------------------------------------------------------
__device__ float g_XF [(size_t)B_ * NX * 256];          // xf^T   [B][Nx][C] (tf32)
__device__ float g_ZFT[(size_t)B_ * NZ * 256];          // zf^T   [B][Nz][C] (tf32)
__device__ float g_XTZ[(size_t)B_ * XTZ_ROWS * 256];    // [xf_trans^T; zf_trans^T]
__device__ float g_ZG [(size_t)B_ * 256 * ZG_LD];       // zf_g  [c][m-pad64]
__device__ float g_XGT[(size_t)B_ * 256 * XGT_LD];      // xf_g  [c][m-pad992]
__device__ float g_CT [(size_t)B_ * CT_ROWS * CT_LD];   // [emb|self|xg] n-major
__device__ float g_PS [(size_t)B_ * NX * PS_LD];        // probs: self + cross
__device__ float g_WR [393216];                         // rounded [Wq|Wg|Ws|Wfi]

// ---------------------------------------------------------------------------
__device__ __forceinline__ uint32_t cvt_tf32(float f) {
    uint32_t r;
    asm("cvt.rna.tf32.f32 %0, %1;" : "=r"(r) : "f"(f));
    return r;
}
__device__ __forceinline__ float round_tf32f(float f) {
    return __uint_as_float(cvt_tf32(f));
}
__device__ __forceinline__ uint32_t smem_u32(const void* p) {
    uint32_t a;
    asm("{ .reg .u64 t; cvta.to.shared.u64 t, %1; cvt.u32.u64 %0, t; }" : "=r"(a) : "l"(p));
    return a;
}
__device__ __forceinline__ void cp16(uint32_t dst, const float* src, int ss) {
    asm volatile("cp.async.cg.shared.global [%0], [%1], 16, %2;"
                 :: "r"(dst), "l"(src), "r"(ss));
}
#define CP_COMMIT() asm volatile("cp.async.commit_group;" ::: "memory")
#define CP_WAIT0()  asm volatile("cp.async.wait_group 0;" ::: "memory")
#define CP_WAIT1()  asm volatile("cp.async.wait_group 1;" ::: "memory")

__device__ __forceinline__ void mma_tf32(float* d, const uint32_t* a, const uint32_t* b) {
    asm volatile(
        "mma.sync.aligned.m16n8k8.row.col.f32.tf32.tf32.f32 "
        "{%0,%1,%2,%3}, {%4,%5,%6,%7}, {%8,%9}, {%0,%1,%2,%3};"
        : "+f"(d[0]), "+f"(d[1]), "+f"(d[2]), "+f"(d[3])
        : "r"(a[0]), "r"(a[1]), "r"(a[2]), "r"(a[3]), "r"(b[0]), "r"(b[1]));
}
__device__ __forceinline__ void ldsm4(uint32_t& r0, uint32_t& r1, uint32_t& r2, uint32_t& r3,
                                      uint32_t addr) {
    asm volatile("ldmatrix.sync.aligned.m8n8.x4.shared.b16 {%0,%1,%2,%3}, [%4];"
                 : "=r"(r0), "=r"(r1), "=r"(r2), "=r"(r3) : "r"(addr));
}

// ---------------------------------------------------------------------------
// cp.async stager: src row-major-k (tf32, ld mult of 4, k-tile within row).
// ---------------------------------------------------------------------------
struct StagerCp {
    const float* p[4];
    uint32_t dst[4];
    int sz[4];
    __device__ __forceinline__ void init(const float* src, int ld, int r0, int rmax, int t) {
#pragma unroll
        for (int i = 0; i < 4; i++) {
            int q = i * 256 + t;
            int row = q >> 3, u = q & 7;
            bool ok = (r0 + row < rmax);
            p[i] = ok ? (src + (size_t)(r0 + row) * ld + u * 4) : src;
            sz[i] = ok ? 16 : 0;
            dst[i] = (uint32_t)(((row << 5) + ((u ^ (row & 7)) << 2)) * 4);
        }
    }
    __device__ __forceinline__ void issue(uint32_t sb) {
#pragma unroll
        for (int i = 0; i < 4; i++) {
            cp16(sb + dst[i], p[i], sz[i]);
            p[i] += BK;
        }
    }
};

// ---------------------------------------------------------------------------
// tf32 GEMM: D[m][n] = epi( sum_k A[m][k] * B[n][k] ), tile 128x128x32,
// 256 threads, 3-stage all-cp.async prefetch-first pipeline, LDSM fragments.
// K compile-time.
// EPI 1: relu(bn per row m), +ROUND optional
// EPI 2: plain (+ROUND)
// EPI 5: col split: c<256 +bias[c] -> D ; c>=256 relu(bn[c-256], bias2) -> D2
//        (n-major, ld CT_LD) AND (if HAS3) channel-major copy -> D3[c-256][m]
// EPI 6: merged logits: c<961 -> D[r][c]; 961<=c<1010 -> D[r][c+31]
// ---------------------------------------------------------------------------
template<int EPI, bool ROUND, bool HAS3, int KK>
__global__ void __launch_bounds__(256, 2) mm(
    const float* __restrict__ A, const float* __restrict__ Bm,
    float* __restrict__ D, float* __restrict__ D2, float* __restrict__ D3,
    const float* __restrict__ bias, const float* __restrict__ bias2,
    const float* __restrict__ gamma, const float* __restrict__ beta,
    const float* __restrict__ mean, const float* __restrict__ var,
    int M, int N, int lda, int ldb, int ldd,
    long abs_, long bbs_, long dbs_, long d2bs_, long d3bs_)
{
    constexpr int T = KK / BK;

    extern __shared__ uint32_t smem[];
    const uint32_t sbyte = smem_u32(smem);

    const int t = threadIdx.x;
    const int wid = t >> 5, lane = t & 31;
    const int warp_m = wid & 3, warp_n = wid >> 2;
    const int qid = lane >> 2, qtid = lane & 3;
    const int b = blockIdx.z;
    const int n0 = blockIdx.x * 128;
    const int m0 = blockIdx.y * BM;

    const float* Ab = A + (long)b * abs_;
    const float* Bb = Bm + (long)b * bbs_;
    float* Db = D + (long)b * dbs_;

    float acc[2][8][4];
#pragma unroll
    for (int i = 0; i < 2; i++)
#pragma unroll
        for (int j = 0; j < 8; j++)
#pragma unroll
            for (int k = 0; k < 4; k++) acc[i][j][k] = 0.f;

    // LDSM per-thread address bases (byte offsets inside a stage's A/B tile).
    const int jm = lane >> 3, r7 = lane & 7;
    const uint32_t aoffb = ((uint32_t)(warp_m * 32 + (jm & 1) * 8 + r7) << 7)
                         + ((uint32_t)(((jm >> 1) ^ (lane & 1))) << 4);
    const uint32_t boffb = ((uint32_t)(warp_n * 64 + (jm >> 1) * 8 + r7) << 7)
                         + ((uint32_t)(((jm & 1) ^ (lane & 1))) << 4);
    const uint32_t rq64 = (uint32_t)(lane & 6) << 4;

    StagerCp sa, sb;
    sa.init(Ab, lda, m0, M, t);
    sb.init(Bb, ldb, n0, N, t);

    auto issueStage = [&](int s) {
        sa.issue(sbyte + s * (STW * 4));
        sb.issue(sbyte + s * (STW * 4) + AW * 4);
        CP_COMMIT();
    };

    issueStage(0);
    if (T > 1) issueStage(1);

    int stg = 0;
#pragma unroll 3
    for (int tt = 0; tt < T; tt++) {
        if (tt + 1 < T) CP_WAIT1(); else CP_WAIT0();
        __syncthreads();

        if (tt + 2 < T) {
            int s2 = stg + 2; if (s2 >= 3) s2 -= 3;
            issueStage(s2);
        }

        const uint32_t sAb = sbyte + (uint32_t)stg * (STW * 4) + aoffb;
        const uint32_t sBb = sbyte + (uint32_t)stg * (STW * 4) + (AW * 4) + boffb;
#pragma unroll
        for (int ks = 0; ks < 4; ks++) {
            const uint32_t tk = ((uint32_t)(32 * ks)) ^ rq64;
            uint32_t afr[2][4];
            ldsm4(afr[0][0], afr[0][1], afr[0][2], afr[0][3], sAb + tk);
            ldsm4(afr[1][0], afr[1][1], afr[1][2], afr[1][3], sAb + tk + 2048);
            uint32_t bfr[8][2];
            ldsm4(bfr[0][0], bfr[0][1], bfr[1][0], bfr[1][1], sBb + tk);
            ldsm4(bfr[2][0], bfr[2][1], bfr[3][0], bfr[3][1], sBb + tk + 2048);
            ldsm4(bfr[4][0], bfr[4][1], bfr[5][0], bfr[5][1], sBb + tk + 4096);
            ldsm4(bfr[6][0], bfr[6][1], bfr[7][0], bfr[7][1], sBb + tk + 6144);
#pragma unroll
            for (int im = 0; im < 2; im++)
#pragma unroll
                for (int jn = 0; jn < 8; jn++)
                    mma_tf32(acc[im][jn], afr[im], bfr[jn]);
        }
        stg++; if (stg == 3) stg = 0;
    }

    // ---- epilogue ----
    const int mb = m0 + warp_m * 32;
    const int nb = n0 + warp_n * 64;

    float scl[2][2], sft[2][2];
    if (EPI == 1) {
#pragma unroll
        for (int im = 0; im < 2; im++)
#pragma unroll
            for (int h = 0; h < 2; h++) {
                int r = mb + im * 16 + qid + h * 8;
                int ri = (r < M) ? r : 0;
                float inv = rsqrtf(var[ri] + 1e-5f);
                float s = gamma[ri] * inv;
                scl[im][h] = s;
                sft[im][h] = (bias[ri] - mean[ri]) * s + beta[ri];
            }
    }

    // EPI5: precompute per-column params once (16 columns per thread)
    float cscl[16], csft[16];
    if (EPI == 5) {
#pragma unroll
        for (int jn = 0; jn < 8; jn++)
#pragma unroll
            for (int e = 0; e < 2; e++) {
                int c = nb + jn * 8 + 2 * qtid + e;
                int idx = jn * 2 + e;
                if (c < 256) {
                    cscl[idx] = 1.f;
                    csft[idx] = bias[c];
                } else {
                    int ci = c - 256;
                    float inv = rsqrtf(var[ci] + 1e-5f);
                    float s = gamma[ci] * inv;
                    cscl[idx] = s;
                    csft[idx] = (bias2[ci] - mean[ci]) * s + beta[ci];
                }
            }
    }

    float* D2b = (EPI == 5) ? (D2 + (long)b * d2bs_) : nullptr;
    float* D3b = (EPI == 5 && HAS3) ? (D3 + (long)b * d3bs_) : nullptr;

#pragma unroll
    for (int im = 0; im < 2; im++) {
#pragma unroll
        for (int jn = 0; jn < 8; jn++) {
            int c0 = nb + jn * 8 + 2 * qtid;
#pragma unroll
            for (int h = 0; h < 2; h++) {
                int r = mb + im * 16 + qid + h * 8;
                if (r >= M) continue;
                float v0 = acc[im][jn][h * 2 + 0];
                float v1 = acc[im][jn][h * 2 + 1];
                if (EPI == 1) {
                    v0 = fmaxf(v0 * scl[im][h] + sft[im][h], 0.f);
                    v1 = fmaxf(v1 * scl[im][h] + sft[im][h], 0.f);
                }
                if (EPI == 5) {
#pragma unroll
                    for (int e = 0; e < 2; e++) {
                        int c = c0 + e;
                        int idx = jn * 2 + e;
                        float v = e ? v1 : v0;
                        v = v * cscl[idx] + csft[idx];
                        if (c >= 256) v = fmaxf(v, 0.f);
                        if (ROUND) v = round_tf32f(v);
                        if (c < 256) {
                            Db[(long)r * ldd + c] = v;
                        } else {
                            D2b[(long)r * CT_LD + (c - 256)] = v;
                            if (HAS3) D3b[(long)(c - 256) * XGT_LD + r] = v;
                        }
                    }
                    continue;
                }
                if (EPI == 6) {
#pragma unroll
                    for (int e = 0; e < 2; e++) {
                        int c = c0 + e;
                        float v = e ? v1 : v0;
                        if (c < 1010) {
                            int dc = (c < 961) ? c : (c + 31);   // cross keys -> cols 992+
                            Db[(long)r * ldd + dc] = v;
                        }
                    }
                    continue;
                }
                if (ROUND) { v0 = round_tf32f(v0); v1 = round_tf32f(v1); }
                if (c0 < N)     Db[(long)r * ldd + c0]     = v0;
                if (c0 + 1 < N) Db[(long)r * ldd + c0 + 1] = v1;
            }
        }
    }
}

// ---------------------------------------------------------------------------
// Dual-segment row softmax over PS rows (ld PS_LD), float4-vectorized seg1:
//   seg1: cols [0, 961)   (thread t owns cols 4t..4t+3; t=240 owns col 960)
//   seg2: cols [992, 1041) (49 cross keys)
// Stores tf32-rounded.
// ---------------------------------------------------------------------------
__global__ void softmax_rows2(float* __restrict__ L)
{
    float* p = L + (size_t)blockIdx.x * PS_LD;
    const int t = threadIdx.x;

    __shared__ float redmax[8];
    __shared__ float redsum[8];

    // ---- segment 1: cols [0, 961) ----
    {
        float r[4];
        if (t < 240) {
            float4 v = *reinterpret_cast<const float4*>(p + 4 * t);
            r[0] = v.x; r[1] = v.y; r[2] = v.z; r[3] = v.w;
        } else if (t == 240) {
            r[0] = p[960]; r[1] = -1e30f; r[2] = -1e30f; r[3] = -1e30f;
        } else {
            r[0] = -1e30f; r[1] = -1e30f; r[2] = -1e30f; r[3] = -1e30f;
        }
        float mx = fmaxf(fmaxf(r[0], r[1]), fmaxf(r[2], r[3]));
#pragma unroll
        for (int off = 16; off; off >>= 1)
            mx = fmaxf(mx, __shfl_xor_sync(0xffffffffu, mx, off));
        if ((t & 31) == 0) redmax[t >> 5] = mx;
        __syncthreads();
        mx = redmax[0];
#pragma unroll
        for (int w = 1; w < 8; w++) mx = fmaxf(mx, redmax[w]);

        float s = 0.f;
#pragma unroll
        for (int i = 0; i < 4; i++) {
            bool ok = (t < 240) || (t == 240 && i == 0);
            r[i] = ok ? __expf(r[i] - mx) : 0.f;
            s += r[i];
        }
#pragma unroll
        for (int off = 16; off; off >>= 1)
            s += __shfl_xor_sync(0xffffffffu, s, off);
        if ((t & 31) == 0) redsum[t >> 5] = s;
        __syncthreads();
        s = 0.f;
#pragma unroll
        for (int w = 0; w < 8; w++) s += redsum[w];

        float inv = 1.f / s;
        if (t < 240) {
            float4 o;
            o.x = round_tf32f(r[0] * inv);
            o.y = round_tf32f(r[1] * inv);
            o.z = round_tf32f(r[2] * inv);
            o.w = round_tf32f(r[3] * inv);
            *reinterpret_cast<float4*>(p + 4 * t) = o;
        } else if (t == 240) {
            p[960] = round_tf32f(r[0] * inv);
        }
    }
    __syncthreads();

    // ---- segment 2: 49 cross keys at cols 992.. ----
    {
        float v = (t < NZ) ? p[992 + t] : -1e30f;
        float mx = v;
#pragma unroll
        for (int off = 16; off; off >>= 1)
            mx = fmaxf(mx, __shfl_xor_sync(0xffffffffu, mx, off));
        if ((t & 31) == 0) redmax[t >> 5] = mx;
        __syncthreads();
        mx = redmax[0];
#pragma unroll
        for (int w = 1; w < 8; w++) mx = fmaxf(mx, redmax[w]);

        float ev = (t < NZ) ? __expf(v - mx) : 0.f;
        float s = ev;
#pragma unroll
        for (int off = 16; off; off >>= 1)
            s += __shfl_xor_sync(0xffffffffu, s, off);
        if ((t & 31) == 0) redsum[t >> 5] = s;
        __syncthreads();
        s = 0.f;
#pragma unroll
        for (int w = 0; w < 8; w++) s += redsum[w];

        if (t < NZ) p[992 + t] = round_tf32f(ev * (1.f / s));
    }
}

// ---------------------------------------------------------------------------
// src [B][256][Ns] -> dst [B][Ns][256], tf32-rounded. Dense batch stride.
// ---------------------------------------------------------------------------
__global__ void transpose_round(const float* __restrict__ src, float* __restrict__ dst, int Ns)
{
    __shared__ float tl[32][33];
    const int b = blockIdx.z;
    const int n0 = blockIdx.x * 32, c0 = blockIdx.y * 32;
    const int tx = threadIdx.x & 31, ty = threadIdx.x >> 5;
    const float* s = src + (size_t)b * 256 * Ns;
    float* d = dst + (size_t)b * Ns * 256;
#pragma unroll
    for (int i = 0; i < 4; i++) {
        int c = c0 + ty + i * 8, n = n0 + tx;
        tl[ty + i * 8][tx] = (n < Ns) ? s[(size_t)c * Ns + n] : 0.f;
    }
    __syncthreads();
#pragma unroll
    for (int i = 0; i < 4; i++) {
        int n = n0 + ty + i * 8, c = c0 + tx;
        if (n < Ns) d[(size_t)n * 256 + c] = round_tf32f(tl[tx][ty + i * 8]);
    }
}

// ---------------------------------------------------------------------------
// Pre-round weights into g_WR: [Wq | Wg | Ws | Wfi]
// ---------------------------------------------------------------------------
__global__ void round_weights(const float* __restrict__ wq, const float* __restrict__ ws,
                              const float* __restrict__ wg, const float* __restrict__ wfi,
                              float* __restrict__ o)
{
    for (int i = blockIdx.x * 256 + threadIdx.x; i < 393216; i += gridDim.x * 256) {
        float v;
        if      (i < 65536)  v = wq [i];
        else if (i < 131072) v = wg [i - 65536];
        else if (i < 196608) v = ws [i - 131072];
        else                 v = wfi[i - 196608];
        o[i] = round_tf32f(v);
    }
}

// ---------------------------------------------------------------------------
extern "C" void kernel_launch(void* const* d_in, const int* in_sizes, int n_in,
                              void* d_out, int out_size)
{
    const float* zf  = (const float*)d_in[0];
    const float* xf  = (const float*)d_in[1];
    const float* Wq  = (const float*)d_in[2];
    const float* bq  = (const float*)d_in[3];
    const float* Ws_ = (const float*)d_in[4];
    const float* bs  = (const float*)d_in[5];
    const float* Wg  = (const float*)d_in[6];
    const float* bg  = (const float*)d_in[7];
    const float* g_gamma = (const float*)d_in[8];
    const float* g_beta  = (const float*)d_in[9];
    const float* g_mean  = (const float*)d_in[10];
    const float* g_var   = (const float*)d_in[11];
    const float* Wfi = (const float*)d_in[12];
    const float* bfi = (const float*)d_in[13];
    const float* fi_gamma = (const float*)d_in[14];
    const float* fi_beta  = (const float*)d_in[15];
    const float* fi_mean  = (const float*)d_in[16];
    const float* fi_var   = (const float*)d_in[17];
    float* out = (float*)d_out;

    float *XF, *ZFT, *XTZ, *ZG, *XGT, *CT, *PS, *WR;
    cudaGetSymbolAddress((void**)&XF,  g_XF);
    cudaGetSymbolAddress((void**)&ZFT, g_ZFT);
    cudaGetSymbolAddress((void**)&XTZ, g_XTZ);
    cudaGetSymbolAddress((void**)&ZG,  g_ZG);
    cudaGetSymbolAddress((void**)&XGT, g_XGT);
    cudaGetSymbolAddress((void**)&CT,  g_CT);
    cudaGetSymbolAddress((void**)&PS,  g_PS);
    cudaGetSymbolAddress((void**)&WR,  g_WR);

#define SETUP(KER) do { \
    cudaFuncSetAttribute(KER, cudaFuncAttributeMaxDynamicSharedMemorySize, SMEMB); \
    cudaFuncSetAttribute(KER, cudaFuncAttributePreferredSharedMemoryCarveout, 100); \
} while (0)
    SETUP((mm<5,true ,true ,256>));
    SETUP((mm<1,true ,false,256>));
    SETUP((mm<5,true ,false,256>));
    SETUP((mm<6,false,false,256>));
    SETUP((mm<2,true ,false,992>));
    SETUP((mm<2,true ,false,64 >));
    SETUP((mm<1,false,false,768>));
#undef SETUP

    const long XF_BS  = (long)NX * 256;
    const long ZFT_BS = (long)NZ * 256;
    const long XTZ_BS = (long)XTZ_ROWS * 256;
    const long ZG_BS  = (long)256 * ZG_LD;
    const long XGT_BS = (long)256 * XGT_LD;
    const long CT_BS  = (long)CT_ROWS * CT_LD;
    const long PS_BS  = (long)NX * PS_LD;
    const long OUT_BS = (long)256 * NX;
    float* SE  = CT + 256;             // self_emb cols
    float* XGc = CT + 512;             // xf_g cols
    float* ZT2 = XTZ + 961 * 256;      // zf_trans^T rows inside XTZ

    // 0) prep
    round_weights<<<256, 256>>>(Wq, Ws_, Wg, Wfi, WR);
    transpose_round<<<dim3(31, 8, B_), 256>>>(xf, XF, NX);
    transpose_round<<<dim3(2, 8, B_), 256>>>(zf, ZFT, NZ);

    // 1) merged conv: cols 0-255 -> XTZ rows 0..960 (+bq);
    //    cols 256-511 -> xf_g (bn+relu) into CATT cols 512-767 AND XGT
    mm<5,true,true,256><<<dim3(4, 8, B_), 256, SMEMB>>>(
        XF, WR, XTZ, XGc, XGT, bq, bg, g_gamma, g_beta, g_mean, g_var,
        NX, 512, 256, 256, 256, XF_BS, 0, XTZ_BS, CT_BS, XGT_BS);
    // 2) zf_g[c][m] = relu(bn(Wg @ zf))
    mm<1,true,false,256><<<dim3(1, 2, B_), 256, SMEMB>>>(
        WR + 65536, ZFT, ZG, nullptr, nullptr, bg, nullptr,
        g_gamma, g_beta, g_mean, g_var,
        256, NZ, 256, 256, ZG_LD, 0, ZFT_BS, ZG_BS, 0, 0);
    // 3) zf_trans^T[m][c] = zf^T @ Ws^T + bs  -> XTZ rows 961..1009
    mm<5,true,false,256><<<dim3(2, 1, B_), 256, SMEMB>>>(
        ZFT, WR + 131072, ZT2, ZT2, ZT2, bs, nullptr,
        nullptr, nullptr, nullptr, nullptr,
        NZ, 256, 256, 256, 256, ZFT_BS, 0, XTZ_BS, 0, 0);
    // 4) merged logits: Q = XTZ rows 0..960, keys = XTZ rows 0..1009.
    //    cols <961 -> PS self; 961..1009 -> PS cols 992.. (cross)
    mm<6,false,false,256><<<dim3(8, 8, B_), 256, SMEMB>>>(
        XTZ, XTZ, PS, nullptr, nullptr, nullptr, nullptr, nullptr, nullptr,
        nullptr, nullptr,
        NX, 1010, 256, 256, PS_LD, XTZ_BS, XTZ_BS, PS_BS, 0, 0);
    // 5) dual-segment softmax (self + cross in one launch, float4 seg1)
    softmax_rows2<<<dim3(B_ * NX), 256>>>(PS);
    // 6) self_emb[n][c] = PS @ XGT^T, K=992
    mm<2,true,false,992><<<dim3(2, 8, B_), 256, SMEMB>>>(
        PS, XGT, SE, nullptr, nullptr, nullptr, nullptr, nullptr, nullptr,
        nullptr, nullptr,
        NX, 256, PS_LD, XGT_LD, CT_LD, PS_BS, XGT_BS, CT_BS, 0, 0);
    // 7) emb[n][c] = PZ @ zf_g^T  (A = PS cols 992.., ld PS_LD), K=64
    mm<2,true,false,64><<<dim3(2, 8, B_), 256, SMEMB>>>(
        PS + 992, ZG, CT, nullptr, nullptr, nullptr, nullptr, nullptr, nullptr,
        nullptr, nullptr,
        NX, 256, PS_LD, ZG_LD, CT_LD, PS_BS, ZG_BS, CT_BS, 0, 0);
    // 8) out = relu(bn(Wfi @ CATT^T)), K=768
    mm<1,false,false,768><<<dim3(8, 2, B_), 256, SMEMB>>>(
        WR + 196608, CT, out, nullptr, nullptr, bfi, nullptr,
        fi_gamma, fi_beta, fi_mean, fi_var,
        256, NX, 768, CT_LD, NX, 0, CT_BS, OUT_BS, 0, 0);
}

// round 17
// speedup vs baseline: 1.2940x; 1.0746x over previous
#include <cuda_runtime.h>
#include <cstdint>

// ---------------------------------------------------------------------------
// Problem constants
// ---------------------------------------------------------------------------
#define B_   32
#define C_   256
#define NX   961
#define NZ   49
#define XTZ_ROWS 1024   // rows 0..960 = xf_trans^T, 961..1009 = zf_trans^T, rest 0
#define ZG_LD  64
#define CT_LD  768      // CATT row stride
#define CT_ROWS 992     // CATT rows padded (zero rows 961..991)
#define PS_LD  1056     // cols 0..960 self logits/probs, 992..1040 cross, rest 0
#define XGT_LD 992      // channel-major xf_g row stride (zero cols 961..991)

#define BM 128
#define BK 32
#define AW 4096                 // A tile words (128*32)
#define STW 8192                // words per stage (A+B)
#define SMEMB (3 * STW * 4)     // 96 KB, 3-stage

// ---------------------------------------------------------------------------
// Scratch (device globals; zero-initialized, never freed)
// ---------------------------------------------------------------------------
__device__ float g_XF [(size_t)B_ * NX * 256];          // xf^T   [B][Nx][C] (tf32)
__device__ float g_ZFT[(size_t)B_ * NZ * 256];          // zf^T   [B][Nz][C] (tf32)
__device__ float g_XTZ[(size_t)B_ * XTZ_ROWS * 256];    // [xf_trans^T; zf_trans^T]
__device__ float g_ZG [(size_t)B_ * 256 * ZG_LD];       // zf_g  [c][m-pad64]
__device__ float g_XGT[(size_t)B_ * 256 * XGT_LD];      // xf_g  [c][m-pad992]
__device__ float g_CT [(size_t)B_ * CT_ROWS * CT_LD];   // [emb|self|xg] n-major
__device__ float g_PS [(size_t)B_ * NX * PS_LD];        // probs: self + cross
__device__ float g_WR [393216];                         // rounded [Wq|Wg|Ws|Wfi]

// ---------------------------------------------------------------------------
__device__ __forceinline__ uint32_t cvt_tf32(float f) {
    uint32_t r;
    asm("cvt.rna.tf32.f32 %0, %1;" : "=r"(r) : "f"(f));
    return r;
}
__device__ __forceinline__ float round_tf32f(float f) {
    return __uint_as_float(cvt_tf32(f));
}
__device__ __forceinline__ uint32_t smem_u32(const void* p) {
    uint32_t a;
    asm("{ .reg .u64 t; cvta.to.shared.u64 t, %1; cvt.u32.u64 %0, t; }" : "=r"(a) : "l"(p));
    return a;
}
__device__ __forceinline__ void cp16(uint32_t dst, const float* src, int ss) {
    asm volatile("cp.async.cg.shared.global [%0], [%1], 16, %2;"
                 :: "r"(dst), "l"(src), "r"(ss));
}
#define CP_COMMIT() asm volatile("cp.async.commit_group;" ::: "memory")
#define CP_WAIT0()  asm volatile("cp.async.wait_group 0;" ::: "memory")
#define CP_WAIT1()  asm volatile("cp.async.wait_group 1;" ::: "memory")

__device__ __forceinline__ void mma_tf32(float* d, const uint32_t* a, const uint32_t* b) {
    asm volatile(
        "mma.sync.aligned.m16n8k8.row.col.f32.tf32.tf32.f32 "
        "{%0,%1,%2,%3}, {%4,%5,%6,%7}, {%8,%9}, {%0,%1,%2,%3};"
        : "+f"(d[0]), "+f"(d[1]), "+f"(d[2]), "+f"(d[3])
        : "r"(a[0]), "r"(a[1]), "r"(a[2]), "r"(a[3]), "r"(b[0]), "r"(b[1]));
}
__device__ __forceinline__ void ldsm4(uint32_t& r0, uint32_t& r1, uint32_t& r2, uint32_t& r3,
                                      uint32_t addr) {
    asm volatile("ldmatrix.sync.aligned.m8n8.x4.shared.b16 {%0,%1,%2,%3}, [%4];"
                 : "=r"(r0), "=r"(r1), "=r"(r2), "=r"(r3) : "r"(addr));
}

// ---------------------------------------------------------------------------
// cp.async stager: src row-major-k (tf32, ld mult of 4, k-tile within row).
// ---------------------------------------------------------------------------
struct StagerCp {
    const float* p[4];
    uint32_t dst[4];
    int sz[4];
    __device__ __forceinline__ void init(const float* src, int ld, int r0, int rmax, int t) {
#pragma unroll
        for (int i = 0; i < 4; i++) {
            int q = i * 256 + t;
            int row = q >> 3, u = q & 7;
            bool ok = (r0 + row < rmax);
            p[i] = ok ? (src + (size_t)(r0 + row) * ld + u * 4) : src;
            sz[i] = ok ? 16 : 0;
            dst[i] = (uint32_t)(((row << 5) + ((u ^ (row & 7)) << 2)) * 4);
        }
    }
    __device__ __forceinline__ void issue(uint32_t sb) {
#pragma unroll
        for (int i = 0; i < 4; i++) {
            cp16(sb + dst[i], p[i], sz[i]);
            p[i] += BK;
        }
    }
};

// ---------------------------------------------------------------------------
// tf32 GEMM: D[m][n] = epi( sum_k A[m][k] * B[n][k] ), tile 128x128x32,
// 256 threads, 3-stage all-cp.async prefetch-first pipeline, LDSM fragments.
// K compile-time.
// EPI 1: relu(bn per row m), +ROUND optional
// EPI 2: plain (+ROUND)
// EPI 5: col split: c<256 +bias[c] -> D ; c>=256 relu(bn[c-256], bias2) -> D2
//        (n-major, ld CT_LD) AND (if HAS3) channel-major copy -> D3[c-256][m]
// EPI 7: symmetric merged logits. Tiles with col-tile < row-tile exit early
//        (mirrored coverage). c<961 -> D[r][c] (+ mirror D[c][r] when n0>m0);
//        961<=c<1010 -> D[r][c+31] (cross, never mirrored).
// ---------------------------------------------------------------------------
template<int EPI, bool ROUND, bool HAS3, int KK>
__global__ void __launch_bounds__(256, 2) mm(
    const float* __restrict__ A, const float* __restrict__ Bm,
    float* __restrict__ D, float* __restrict__ D2, float* __restrict__ D3,
    const float* __restrict__ bias, const float* __restrict__ bias2,
    const float* __restrict__ gamma, const float* __restrict__ beta,
    const float* __restrict__ mean, const float* __restrict__ var,
    int M, int N, int lda, int ldb, int ldd,
    long abs_, long bbs_, long dbs_, long d2bs_, long d3bs_)
{
    constexpr int T = KK / BK;

    const int n0 = blockIdx.x * 128;
    const int m0 = blockIdx.y * BM;
    if (EPI == 7 && n0 < m0) return;   // lower-triangle tiles covered by mirror

    extern __shared__ uint32_t smem[];
    const uint32_t sbyte = smem_u32(smem);

    const int t = threadIdx.x;
    const int wid = t >> 5, lane = t & 31;
    const int warp_m = wid & 3, warp_n = wid >> 2;
    const int qid = lane >> 2, qtid = lane & 3;
    const int b = blockIdx.z;

    const float* Ab = A + (long)b * abs_;
    const float* Bb = Bm + (long)b * bbs_;
    float* Db = D + (long)b * dbs_;

    float acc[2][8][4];
#pragma unroll
    for (int i = 0; i < 2; i++)
#pragma unroll
        for (int j = 0; j < 8; j++)
#pragma unroll
            for (int k = 0; k < 4; k++) acc[i][j][k] = 0.f;

    // LDSM per-thread address bases (byte offsets inside a stage's A/B tile).
    const int jm = lane >> 3, r7 = lane & 7;
    const uint32_t aoffb = ((uint32_t)(warp_m * 32 + (jm & 1) * 8 + r7) << 7)
                         + ((uint32_t)(((jm >> 1) ^ (lane & 1))) << 4);
    const uint32_t boffb = ((uint32_t)(warp_n * 64 + (jm >> 1) * 8 + r7) << 7)
                         + ((uint32_t)(((jm & 1) ^ (lane & 1))) << 4);
    const uint32_t rq64 = (uint32_t)(lane & 6) << 4;

    StagerCp sa, sb;
    sa.init(Ab, lda, m0, M, t);
    sb.init(Bb, ldb, n0, N, t);

    auto issueStage = [&](int s) {
        sa.issue(sbyte + s * (STW * 4));
        sb.issue(sbyte + s * (STW * 4) + AW * 4);
        CP_COMMIT();
    };

    issueStage(0);
    if (T > 1) issueStage(1);

    int stg = 0;
#pragma unroll 3
    for (int tt = 0; tt < T; tt++) {
        if (tt + 1 < T) CP_WAIT1(); else CP_WAIT0();
        __syncthreads();

        if (tt + 2 < T) {
            int s2 = stg + 2; if (s2 >= 3) s2 -= 3;
            issueStage(s2);
        }

        const uint32_t sAb = sbyte + (uint32_t)stg * (STW * 4) + aoffb;
        const uint32_t sBb = sbyte + (uint32_t)stg * (STW * 4) + (AW * 4) + boffb;
#pragma unroll
        for (int ks = 0; ks < 4; ks++) {
            const uint32_t tk = ((uint32_t)(32 * ks)) ^ rq64;
            uint32_t afr[2][4];
            ldsm4(afr[0][0], afr[0][1], afr[0][2], afr[0][3], sAb + tk);
            ldsm4(afr[1][0], afr[1][1], afr[1][2], afr[1][3], sAb + tk + 2048);
            uint32_t bfr[8][2];
            ldsm4(bfr[0][0], bfr[0][1], bfr[1][0], bfr[1][1], sBb + tk);
            ldsm4(bfr[2][0], bfr[2][1], bfr[3][0], bfr[3][1], sBb + tk + 2048);
            ldsm4(bfr[4][0], bfr[4][1], bfr[5][0], bfr[5][1], sBb + tk + 4096);
            ldsm4(bfr[6][0], bfr[6][1], bfr[7][0], bfr[7][1], sBb + tk + 6144);
#pragma unroll
            for (int im = 0; im < 2; im++)
#pragma unroll
                for (int jn = 0; jn < 8; jn++)
                    mma_tf32(acc[im][jn], afr[im], bfr[jn]);
        }
        stg++; if (stg == 3) stg = 0;
    }

    // ---- epilogue ----
    const int mb = m0 + warp_m * 32;
    const int nb = n0 + warp_n * 64;

    float scl[2][2], sft[2][2];
    if (EPI == 1) {
#pragma unroll
        for (int im = 0; im < 2; im++)
#pragma unroll
            for (int h = 0; h < 2; h++) {
                int r = mb + im * 16 + qid + h * 8;
                int ri = (r < M) ? r : 0;
                float inv = rsqrtf(var[ri] + 1e-5f);
                float s = gamma[ri] * inv;
                scl[im][h] = s;
                sft[im][h] = (bias[ri] - mean[ri]) * s + beta[ri];
            }
    }

    // EPI5: precompute per-column params once (16 columns per thread)
    float cscl[16], csft[16];
    if (EPI == 5) {
#pragma unroll
        for (int jn = 0; jn < 8; jn++)
#pragma unroll
            for (int e = 0; e < 2; e++) {
                int c = nb + jn * 8 + 2 * qtid + e;
                int idx = jn * 2 + e;
                if (c < 256) {
                    cscl[idx] = 1.f;
                    csft[idx] = bias[c];
                } else {
                    int ci = c - 256;
                    float inv = rsqrtf(var[ci] + 1e-5f);
                    float s = gamma[ci] * inv;
                    cscl[idx] = s;
                    csft[idx] = (bias2[ci] - mean[ci]) * s + beta[ci];
                }
            }
    }

    float* D2b = (EPI == 5) ? (D2 + (long)b * d2bs_) : nullptr;
    float* D3b = (EPI == 5 && HAS3) ? (D3 + (long)b * d3bs_) : nullptr;

    const bool mirror = (EPI == 7) && (n0 > m0);

#pragma unroll
    for (int im = 0; im < 2; im++) {
#pragma unroll
        for (int jn = 0; jn < 8; jn++) {
            int c0 = nb + jn * 8 + 2 * qtid;
#pragma unroll
            for (int h = 0; h < 2; h++) {
                int r = mb + im * 16 + qid + h * 8;
                if (r >= M) continue;
                float v0 = acc[im][jn][h * 2 + 0];
                float v1 = acc[im][jn][h * 2 + 1];
                if (EPI == 1) {
                    v0 = fmaxf(v0 * scl[im][h] + sft[im][h], 0.f);
                    v1 = fmaxf(v1 * scl[im][h] + sft[im][h], 0.f);
                }
                if (EPI == 5) {
#pragma unroll
                    for (int e = 0; e < 2; e++) {
                        int c = c0 + e;
                        int idx = jn * 2 + e;
                        float v = e ? v1 : v0;
                        v = v * cscl[idx] + csft[idx];
                        if (c >= 256) v = fmaxf(v, 0.f);
                        if (ROUND) v = round_tf32f(v);
                        if (c < 256) {
                            Db[(long)r * ldd + c] = v;
                        } else {
                            D2b[(long)r * CT_LD + (c - 256)] = v;
                            if (HAS3) D3b[(long)(c - 256) * XGT_LD + r] = v;
                        }
                    }
                    continue;
                }
                if (EPI == 7) {
#pragma unroll
                    for (int e = 0; e < 2; e++) {
                        int c = c0 + e;
                        float v = e ? v1 : v0;
                        if (c < 1010) {
                            if (c < 961) {
                                Db[(long)r * ldd + c] = v;
                                if (mirror) Db[(long)c * ldd + r] = v;
                            } else {
                                Db[(long)r * ldd + (c + 31)] = v;
                            }
                        }
                    }
                    continue;
                }
                if (ROUND) { v0 = round_tf32f(v0); v1 = round_tf32f(v1); }
                if (c0 < N)     Db[(long)r * ldd + c0]     = v0;
                if (c0 + 1 < N) Db[(long)r * ldd + c0 + 1] = v1;
            }
        }
    }
}

// ---------------------------------------------------------------------------
// Dual-segment row softmax over PS rows (ld PS_LD), float4-vectorized seg1:
//   seg1: cols [0, 961)   (thread t owns cols 4t..4t+3; t=240 owns col 960)
//   seg2: cols [992, 1041) (49 cross keys)
// Stores tf32-rounded.
// ---------------------------------------------------------------------------
__global__ void softmax_rows2(float* __restrict__ L)
{
    float* p = L + (size_t)blockIdx.x * PS_LD;
    const int t = threadIdx.x;

    __shared__ float redmax[8];
    __shared__ float redsum[8];

    // ---- segment 1: cols [0, 961) ----
    {
        float r[4];
        if (t < 240) {
            float4 v = *reinterpret_cast<const float4*>(p + 4 * t);
            r[0] = v.x; r[1] = v.y; r[2] = v.z; r[3] = v.w;
        } else if (t == 240) {
            r[0] = p[960]; r[1] = -1e30f; r[2] = -1e30f; r[3] = -1e30f;
        } else {
            r[0] = -1e30f; r[1] = -1e30f; r[2] = -1e30f; r[3] = -1e30f;
        }
        float mx = fmaxf(fmaxf(r[0], r[1]), fmaxf(r[2], r[3]));
#pragma unroll
        for (int off = 16; off; off >>= 1)
            mx = fmaxf(mx, __shfl_xor_sync(0xffffffffu, mx, off));
        if ((t & 31) == 0) redmax[t >> 5] = mx;
        __syncthreads();
        mx = redmax[0];
#pragma unroll
        for (int w = 1; w < 8; w++) mx = fmaxf(mx, redmax[w]);

        float s = 0.f;
#pragma unroll
        for (int i = 0; i < 4; i++) {
            bool ok = (t < 240) || (t == 240 && i == 0);
            r[i] = ok ? __expf(r[i] - mx) : 0.f;
            s += r[i];
        }
#pragma unroll
        for (int off = 16; off; off >>= 1)
            s += __shfl_xor_sync(0xffffffffu, s, off);
        if ((t & 31) == 0) redsum[t >> 5] = s;
        __syncthreads();
        s = 0.f;
#pragma unroll
        for (int w = 0; w < 8; w++) s += redsum[w];

        float inv = 1.f / s;
        if (t < 240) {
            float4 o;
            o.x = round_tf32f(r[0] * inv);
            o.y = round_tf32f(r[1] * inv);
            o.z = round_tf32f(r[2] * inv);
            o.w = round_tf32f(r[3] * inv);
            *reinterpret_cast<float4*>(p + 4 * t) = o;
        } else if (t == 240) {
            p[960] = round_tf32f(r[0] * inv);
        }
    }
    __syncthreads();

    // ---- segment 2: 49 cross keys at cols 992.. ----
    {
        float v = (t < NZ) ? p[992 + t] : -1e30f;
        float mx = v;
#pragma unroll
        for (int off = 16; off; off >>= 1)
            mx = fmaxf(mx, __shfl_xor_sync(0xffffffffu, mx, off));
        if ((t & 31) == 0) redmax[t >> 5] = mx;
        __syncthreads();
        mx = redmax[0];
#pragma unroll
        for (int w = 1; w < 8; w++) mx = fmaxf(mx, redmax[w]);

        float ev = (t < NZ) ? __expf(v - mx) : 0.f;
        float s = ev;
#pragma unroll
        for (int off = 16; off; off >>= 1)
            s += __shfl_xor_sync(0xffffffffu, s, off);
        if ((t & 31) == 0) redsum[t >> 5] = s;
        __syncthreads();
        s = 0.f;
#pragma unroll
        for (int w = 0; w < 8; w++) s += redsum[w];

        if (t < NZ) p[992 + t] = round_tf32f(ev * (1.f / s));
    }
}

// ---------------------------------------------------------------------------
// src [B][256][Ns] -> dst [B][Ns][256], tf32-rounded. Dense batch stride.
// ---------------------------------------------------------------------------
__global__ void transpose_round(const float* __restrict__ src, float* __restrict__ dst, int Ns)
{
    __shared__ float tl[32][33];
    const int b = blockIdx.z;
    const int n0 = blockIdx.x * 32, c0 = blockIdx.y * 32;
    const int tx = threadIdx.x & 31, ty = threadIdx.x >> 5;
    const float* s = src + (size_t)b * 256 * Ns;
    float* d = dst + (size_t)b * Ns * 256;
#pragma unroll
    for (int i = 0; i < 4; i++) {
        int c = c0 + ty + i * 8, n = n0 + tx;
        tl[ty + i * 8][tx] = (n < Ns) ? s[(size_t)c * Ns + n] : 0.f;
    }
    __syncthreads();
#pragma unroll
    for (int i = 0; i < 4; i++) {
        int n = n0 + ty + i * 8, c = c0 + tx;
        if (n < Ns) d[(size_t)n * 256 + c] = round_tf32f(tl[tx][ty + i * 8]);
    }
}

// ---------------------------------------------------------------------------
// Pre-round weights into g_WR: [Wq | Wg | Ws | Wfi]
// ---------------------------------------------------------------------------
__global__ void round_weights(const float* __restrict__ wq, const float* __restrict__ ws,
                              const float* __restrict__ wg, const float* __restrict__ wfi,
                              float* __restrict__ o)
{
    for (int i = blockIdx.x * 256 + threadIdx.x; i < 393216; i += gridDim.x * 256) {
        float v;
        if      (i < 65536)  v = wq [i];
        else if (i < 131072) v = wg [i - 65536];
        else if (i < 196608) v = ws [i - 131072];
        else                 v = wfi[i - 196608];
        o[i] = round_tf32f(v);
    }
}

// ---------------------------------------------------------------------------
extern "C" void kernel_launch(void* const* d_in, const int* in_sizes, int n_in,
                              void* d_out, int out_size)
{
    const float* zf  = (const float*)d_in[0];
    const float* xf  = (const float*)d_in[1];
    const float* Wq  = (const float*)d_in[2];
    const float* bq  = (const float*)d_in[3];
    const float* Ws_ = (const float*)d_in[4];
    const float* bs  = (const float*)d_in[5];
    const float* Wg  = (const float*)d_in[6];
    const float* bg  = (const float*)d_in[7];
    const float* g_gamma = (const float*)d_in[8];
    const float* g_beta  = (const float*)d_in[9];
    const float* g_mean  = (const float*)d_in[10];
    const float* g_var   = (const float*)d_in[11];
    const float* Wfi = (const float*)d_in[12];
    const float* bfi = (const float*)d_in[13];
    const float* fi_gamma = (const float*)d_in[14];
    const float* fi_beta  = (const float*)d_in[15];
    const float* fi_mean  = (const float*)d_in[16];
    const float* fi_var   = (const float*)d_in[17];
    float* out = (float*)d_out;

    float *XF, *ZFT, *XTZ, *ZG, *XGT, *CT, *PS, *WR;
    cudaGetSymbolAddress((void**)&XF,  g_XF);
    cudaGetSymbolAddress((void**)&ZFT, g_ZFT);
    cudaGetSymbolAddress((void**)&XTZ, g_XTZ);
    cudaGetSymbolAddress((void**)&ZG,  g_ZG);
    cudaGetSymbolAddress((void**)&XGT, g_XGT);
    cudaGetSymbolAddress((void**)&CT,  g_CT);
    cudaGetSymbolAddress((void**)&PS,  g_PS);
    cudaGetSymbolAddress((void**)&WR,  g_WR);

#define SETUP(KER) do { \
    cudaFuncSetAttribute(KER, cudaFuncAttributeMaxDynamicSharedMemorySize, SMEMB); \
    cudaFuncSetAttribute(KER, cudaFuncAttributePreferredSharedMemoryCarveout, 100); \
} while (0)
    SETUP((mm<5,true ,true ,256>));
    SETUP((mm<1,true ,false,256>));
    SETUP((mm<5,true ,false,256>));
    SETUP((mm<7,false,false,256>));
    SETUP((mm<2,true ,false,992>));
    SETUP((mm<2,true ,false,64 >));
    SETUP((mm<1,false,false,768>));
#undef SETUP

    const long XF_BS  = (long)NX * 256;
    const long ZFT_BS = (long)NZ * 256;
    const long XTZ_BS = (long)XTZ_ROWS * 256;
    const long ZG_BS  = (long)256 * ZG_LD;
    const long XGT_BS = (long)256 * XGT_LD;
    const long CT_BS  = (long)CT_ROWS * CT_LD;
    const long PS_BS  = (long)NX * PS_LD;
    const long OUT_BS = (long)256 * NX;
    float* SE  = CT + 256;             // self_emb cols
    float* XGc = CT + 512;             // xf_g cols
    float* ZT2 = XTZ + 961 * 256;      // zf_trans^T rows inside XTZ

    // 0) prep
    round_weights<<<256, 256>>>(Wq, Ws_, Wg, Wfi, WR);
    transpose_round<<<dim3(31, 8, B_), 256>>>(xf, XF, NX);
    transpose_round<<<dim3(2, 8, B_), 256>>>(zf, ZFT, NZ);

    // 1) merged conv: cols 0-255 -> XTZ rows 0..960 (+bq);
    //    cols 256-511 -> xf_g (bn+relu) into CATT cols 512-767 AND XGT
    mm<5,true,true,256><<<dim3(4, 8, B_), 256, SMEMB>>>(
        XF, WR, XTZ, XGc, XGT, bq, bg, g_gamma, g_beta, g_mean, g_var,
        NX, 512, 256, 256, 256, XF_BS, 0, XTZ_BS, CT_BS, XGT_BS);
    // 2) zf_g[c][m] = relu(bn(Wg @ zf))
    mm<1,true,false,256><<<dim3(1, 2, B_), 256, SMEMB>>>(
        WR + 65536, ZFT, ZG, nullptr, nullptr, bg, nullptr,
        g_gamma, g_beta, g_mean, g_var,
        256, NZ, 256, 256, ZG_LD, 0, ZFT_BS, ZG_BS, 0, 0);
    // 3) zf_trans^T[m][c] = zf^T @ Ws^T + bs  -> XTZ rows 961..1009
    mm<5,true,false,256><<<dim3(2, 1, B_), 256, SMEMB>>>(
        ZFT, WR + 131072, ZT2, ZT2, ZT2, bs, nullptr,
        nullptr, nullptr, nullptr, nullptr,
        NZ, 256, 256, 256, 256, ZFT_BS, 0, XTZ_BS, 0, 0);
    // 4) merged symmetric logits: lower-triangle tiles skipped, mirrored in
    //    epilogue (bitwise-exact: XT@XT^T). Cross cols -> PS cols 992.. .
    mm<7,false,false,256><<<dim3(8, 8, B_), 256, SMEMB>>>(
        XTZ, XTZ, PS, nullptr, nullptr, nullptr, nullptr, nullptr, nullptr,
        nullptr, nullptr,
        NX, 1010, 256, 256, PS_LD, XTZ_BS, XTZ_BS, PS_BS, 0, 0);
    // 5) dual-segment softmax (self + cross in one launch, float4 seg1)
    softmax_rows2<<<dim3(B_ * NX), 256>>>(PS);
    // 6) self_emb[n][c] = PS @ XGT^T, K=992
    mm<2,true,false,992><<<dim3(2, 8, B_), 256, SMEMB>>>(
        PS, XGT, SE, nullptr, nullptr, nullptr, nullptr, nullptr, nullptr,
        nullptr, nullptr,
        NX, 256, PS_LD, XGT_LD, CT_LD, PS_BS, XGT_BS, CT_BS, 0, 0);
    // 7) emb[n][c] = PZ @ zf_g^T  (A = PS cols 992.., ld PS_LD), K=64
    mm<2,true,false,64><<<dim3(2, 8, B_), 256, SMEMB>>>(
        PS + 992, ZG, CT, nullptr, nullptr, nullptr, nullptr, nullptr, nullptr,
        nullptr, nullptr,
        NX, 256, PS_LD, ZG_LD, CT_LD, PS_BS, ZG_BS, CT_BS, 0, 0);
    // 8) out = relu(bn(Wfi @ CATT^T)), K=768
    mm<1,false,false,768><<<dim3(8, 2, B_), 256, SMEMB>>>(
        WR + 196608, CT, out, nullptr, nullptr, bfi, nullptr,
        fi_gamma, fi_beta, fi_mean, fi_var,
        256, NX, 768, CT_LD, NX, 0, CT_BS, OUT_BS, 0, 0);
}